// round 7
// baseline (speedup 1.0000x reference)
#include <cuda_runtime.h>
#include <cuda_bf16.h>
#include <math.h>

#define BB   4
#define LL   1024
#define HIDD 768
#define HH   12
#define DD   64
#define BH   (BB*HH)

// ---- scratch (device globals; no allocation allowed) ----
__device__ float g_q[BH * LL * DD];                        // [bh, l, d] (pre-scaled 0.125)
__device__ float g_k[BH * LL * DD];                        // [bh, l, d]
__device__ float g_v[BH * LL * DD];                        // [bh, l, d]
__device__ __nv_bfloat16 g_biasq[(size_t)BH * LL * LL];    // [bh, l, r] = qS/8 + mask
__device__ __nv_bfloat16 g_biaskT[(size_t)BH * LL * LL];   // [bh, r, l] = kS/8

// ---------------- helpers ----------------
__device__ __forceinline__ unsigned tf32cvt(float x) {
    unsigned u;
    asm("cvt.rna.tf32.f32 %0, %1;" : "=r"(u) : "f"(x));
    return u;
}
__device__ __forceinline__ void mma_tf32(float& c0, float& c1, float& c2, float& c3,
                                         unsigned a0, unsigned a1, unsigned a2, unsigned a3,
                                         unsigned b0, unsigned b1) {
    asm("mma.sync.aligned.m16n8k8.row.col.f32.tf32.tf32.f32 "
        "{%0,%1,%2,%3},{%4,%5,%6,%7},{%8,%9},{%0,%1,%2,%3};"
        : "+f"(c0), "+f"(c1), "+f"(c2), "+f"(c3)
        : "r"(a0), "r"(a1), "r"(a2), "r"(a3), "r"(b0), "r"(b1));
}
__device__ __forceinline__ void cp16(const void* smem_dst, const void* gsrc) {
    unsigned sa = (unsigned)__cvta_generic_to_shared(smem_dst);
    asm volatile("cp.async.cg.shared.global [%0], [%1], 16;" :: "r"(sa), "l"(gsrc));
}

// ============================================================================
// K1: QKV projection, tf32 mma.  blockIdx.z selects q/k/v.
// ============================================================================
__global__ __launch_bounds__(256) void qkv_mma_kernel(
    const float* __restrict__ X,
    const float* __restrict__ Wq, const float* __restrict__ bq,
    const float* __restrict__ Wk, const float* __restrict__ bk,
    const float* __restrict__ Wv, const float* __restrict__ bv)
{
    __shared__ unsigned Xs[64][68];
    __shared__ unsigned Ws[64][68];

    const int which = blockIdx.z;
    const float* W    = (which == 0) ? Wq : (which == 1) ? Wk : Wv;
    const float* bias = (which == 0) ? bq : (which == 1) ? bk : bv;

    const int tid  = threadIdx.x;
    const int warp = tid >> 5;
    const int lane = tid & 31;
    const int m0 = blockIdx.x * 64;
    const int n0 = blockIdx.y * 64;
    const int mstrip = (warp & 3) * 16;
    const int nh     = (warp >> 2) * 32;

    float acc[4][4];
#pragma unroll
    for (int i = 0; i < 4; i++)
#pragma unroll
        for (int j = 0; j < 4; j++) acc[i][j] = 0.f;

    for (int k0 = 0; k0 < HIDD; k0 += 64) {
        __syncthreads();
#pragma unroll
        for (int i = 0; i < 4; i++) {
            const int idx = tid + i * 256;
            const int row = idx >> 4;
            const int c4  = idx & 15;
            float4 xv = *(const float4*)(X + (size_t)(m0 + row) * HIDD + k0 + c4 * 4);
            float4 wv = *(const float4*)(W + (size_t)(n0 + row) * HIDD + k0 + c4 * 4);
            Xs[row][c4 * 4 + 0] = tf32cvt(xv.x); Xs[row][c4 * 4 + 1] = tf32cvt(xv.y);
            Xs[row][c4 * 4 + 2] = tf32cvt(xv.z); Xs[row][c4 * 4 + 3] = tf32cvt(xv.w);
            Ws[row][c4 * 4 + 0] = tf32cvt(wv.x); Ws[row][c4 * 4 + 1] = tf32cvt(wv.y);
            Ws[row][c4 * 4 + 2] = tf32cvt(wv.z); Ws[row][c4 * 4 + 3] = tf32cvt(wv.w);
        }
        __syncthreads();
#pragma unroll
        for (int ks = 0; ks < 8; ks++) {
            const int kc = ks * 8 + (lane & 3);
            unsigned a0 = Xs[mstrip + (lane >> 2)][kc];
            unsigned a1 = Xs[mstrip + (lane >> 2) + 8][kc];
            unsigned a2 = Xs[mstrip + (lane >> 2)][kc + 4];
            unsigned a3 = Xs[mstrip + (lane >> 2) + 8][kc + 4];
#pragma unroll
            for (int nt = 0; nt < 4; nt++) {
                const int nb = nh + nt * 8;
                unsigned b0 = Ws[nb + (lane >> 2)][kc];
                unsigned b1 = Ws[nb + (lane >> 2)][kc + 4];
                mma_tf32(acc[nt][0], acc[nt][1], acc[nt][2], acc[nt][3],
                         a0, a1, a2, a3, b0, b1);
            }
        }
    }

    float* out = (which == 0) ? g_q : (which == 1) ? g_k : g_v;
    const float scale = (which == 0) ? 0.125f : 1.0f;
    const int row0 = m0 + mstrip + (lane >> 2);
#pragma unroll
    for (int nt = 0; nt < 4; nt++) {
        const int col = n0 + nh + nt * 8 + 2 * (lane & 3);
        const int h = col >> 6;
        const int d = col & 63;
#pragma unroll
        for (int half = 0; half < 2; half++) {
            const int row = row0 + half * 8;
            const int b_idx = row >> 10;
            const int l     = row & (LL - 1);
            float2 r;
            r.x = (acc[nt][2 * half + 0] + bias[col + 0]) * scale;
            r.y = (acc[nt][2 * half + 1] + bias[col + 1]) * scale;
            *(float2*)&out[(((size_t)b_idx * HH + h) * LL + l) * DD + d] = r;
        }
    }
}

// ============================================================================
// K2: streaming structure-bias GEMM.  Block = (f, variant).  A row resident,
// S streamed over 8 n-chunks of 128 via cp.async double buffer.
//  variant 0 (f=l): g_biasq[bh, f, n]  = q[bh,f,:].S[f,n,:] + mask[b,n]
//  variant 1 (f=r): g_biaskT[bh, f, n] = 0.125 * k[bh,f,:].S[n,f,:]
// ============================================================================
#define BSW 68
#define BIAS_SMEM_FLOATS (4352 + 2 * 8704)   // As 64x68 + 2x S buf 128x68 = 87040 B

__global__ __launch_bounds__(256) void bias_stream_kernel(
    const float* __restrict__ S, const float* __restrict__ mask)
{
    extern __shared__ float bsm[];
    unsigned* As = (unsigned*)bsm;                 // 64 x 68 (tf32 bits)
    float* Sb0 = bsm + 4352;
    float* Sb1 = bsm + 4352 + 8704;

    const int tid  = threadIdx.x;
    const int warp = tid >> 5;
    const int lane = tid & 31;
    const int f       = blockIdx.x;
    const int variant = blockIdx.y;
    const float* Aop = (variant == 0) ? g_q : g_k;

    const int mstrip = (warp & 3) * 16;
    const int nhalf  = (warp >> 2) * 64;
    const int arow   = mstrip + (lane >> 2);

    // A tile: 48 real bh rows (zero-pad to 64), tf32
    for (int idx = tid; idx < 64 * 16; idx += 256) {
        const int row = idx >> 4;
        const int c4  = idx & 15;
        if (row < BH) {
            float4 av = *(const float4*)(Aop + ((size_t)row * LL + f) * DD + c4 * 4);
            As[row * BSW + c4 * 4 + 0] = tf32cvt(av.x);
            As[row * BSW + c4 * 4 + 1] = tf32cvt(av.y);
            As[row * BSW + c4 * 4 + 2] = tf32cvt(av.z);
            As[row * BSW + c4 * 4 + 3] = tf32cvt(av.w);
        } else {
            As[row * BSW + c4 * 4 + 0] = 0u; As[row * BSW + c4 * 4 + 1] = 0u;
            As[row * BSW + c4 * 4 + 2] = 0u; As[row * BSW + c4 * 4 + 3] = 0u;
        }
    }

    auto stageS = [&](int n0, int db) {
        float* dst = db ? Sb1 : Sb0;
#pragma unroll
        for (int i = 0; i < 8; i++) {
            const int idx = tid + i * 256;
            const int row = idx >> 4;       // 0..127 (n within chunk)
            const int seg = idx & 15;
            size_t soff = (variant == 0)
                ? (((size_t)f * LL + n0 + row) * DD + seg * 4)
                : (((size_t)(n0 + row) * LL + f) * DD + seg * 4);
            cp16(&dst[row * BSW + seg * 4], S + soff);
        }
        asm volatile("cp.async.commit_group;" ::: "memory");
    };

    stageS(0, 0);

    for (int nc = 0; nc < 8; nc++) {
        const int cur = nc & 1;
        const int n0 = nc * 128;
        float* Sc = cur ? Sb1 : Sb0;

        asm volatile("cp.async.wait_group 0;" ::: "memory");
        __syncthreads();                    // chunk cur ready; other buf free
        if (nc + 1 < 8) stageS((nc + 1) * 128, cur ^ 1);

        // convert S chunk tf32 in place
#pragma unroll
        for (int i = 0; i < 32; i++) {
            const int idx = tid + i * 256;
            const int row = idx >> 6;
            const int col = idx & 63;
            Sc[row * BSW + col] = __uint_as_float(tf32cvt(Sc[row * BSW + col]));
        }
        __syncthreads();

        float acc[8][4];
#pragma unroll
        for (int i = 0; i < 8; i++)
#pragma unroll
            for (int j = 0; j < 4; j++) acc[i][j] = 0.f;

#pragma unroll
        for (int ks = 0; ks < 8; ks++) {
            const int kc = ks * 8 + (lane & 3);
            unsigned a0 = As[arow * BSW + kc];
            unsigned a1 = As[(arow + 8) * BSW + kc];
            unsigned a2 = As[arow * BSW + kc + 4];
            unsigned a3 = As[(arow + 8) * BSW + kc + 4];
#pragma unroll
            for (int nt = 0; nt < 8; nt++) {
                const int nb = nhalf + nt * 8 + (lane >> 2);
                unsigned b0 = __float_as_uint(Sc[nb * BSW + kc]);
                unsigned b1 = __float_as_uint(Sc[nb * BSW + kc + 4]);
                mma_tf32(acc[nt][0], acc[nt][1], acc[nt][2], acc[nt][3],
                         a0, a1, a2, a3, b0, b1);
            }
        }

        // store bf16
#pragma unroll
        for (int nt = 0; nt < 8; nt++) {
            const int gcol = n0 + nhalf + nt * 8 + 2 * (lane & 3);
#pragma unroll
            for (int half = 0; half < 2; half++) {
                const int bh = arow + half * 8;
                if (bh >= BH) continue;
                if (variant == 0) {
                    const int b_idx = bh / HH;
                    __nv_bfloat162 bv = __floats2bfloat162_rn(
                        acc[nt][2 * half + 0] + mask[b_idx * LL + gcol + 0],
                        acc[nt][2 * half + 1] + mask[b_idx * LL + gcol + 1]);
                    *(__nv_bfloat162*)&g_biasq[((size_t)bh * LL + f) * LL + gcol] = bv;
                } else {
                    __nv_bfloat162 bv = __floats2bfloat162_rn(
                        acc[nt][2 * half + 0] * 0.125f,
                        acc[nt][2 * half + 1] * 0.125f);
                    *(__nv_bfloat162*)&g_biaskT[((size_t)bh * LL + f) * LL + gcol] = bv;
                }
            }
        }
    }
}

// ============================================================================
// K3: fused flash attention, cp.async double-buffered, per-chunk tf32
// pre-conversion (K in place, V split hi/lo).  P@V compensated (3 mmas).
// ============================================================================
#define RC      32
#define SPW     36
#define QSW     68

// smem layout (float units)
#define OFF_QS    0                       // 64*68 = 4352
#define OFF_KS0   4352                    // 32*68 = 2176
#define OFF_KS1   6528
#define OFF_VR0   8704
#define OFF_VR1   10880
#define OFF_VLO   13056                   // 32*68 = 2176
#define OFF_SP    15232                   // 64*36 = 2304
#define OFF_PL    17536
#define OFF_BQ0   19840                   // 64*40 bf16 = 1280 floats
#define OFF_BQ1   21120
#define OFF_TS    22400                   // 64*34 bf16 = 1088 floats
#define OFF_MS    23488
#define OFF_SU    23552
#define OFF_SC    23616
#define SMEM_FLOATS 23680                 // 94720 B

__global__ __launch_bounds__(256) void fused_attn_kernel(float* __restrict__ out)
{
    extern __shared__ float sm[];
    float* Qs  = sm + OFF_QS;
    float* Vlo = sm + OFF_VLO;
    float* Sp  = sm + OFF_SP;
    float* Pl  = sm + OFF_PL;
    float* m_state   = sm + OFF_MS;
    float* sum_state = sm + OFF_SU;
    float* scalef    = sm + OFF_SC;

    const int tid  = threadIdx.x;
    const int warp = tid >> 5;
    const int lane = tid & 31;
    const int bh   = blockIdx.y;
    const int l0   = blockIdx.x * 64;

    const int mstrip = (warp & 3) * 16;
    const int nh2    = (warp >> 2) * 16;   // qk N = 32
    const int nhpv   = (warp >> 2) * 32;   // pv N = 64
    const int arow   = mstrip + (lane >> 2);
    const int kcl    = lane & 3;

    // ---- prologue: Q tile -> tf32 smem ----
#pragma unroll
    for (int i = 0; i < 4; i++) {
        const int idx = tid + i * 256;
        const int row = idx >> 4;
        const int c4  = idx & 15;
        float4 qv = *(const float4*)(g_q + ((size_t)bh * LL + l0 + row) * DD + c4 * 4);
        Qs[row * QSW + c4 * 4 + 0] = __uint_as_float(tf32cvt(qv.x));
        Qs[row * QSW + c4 * 4 + 1] = __uint_as_float(tf32cvt(qv.y));
        Qs[row * QSW + c4 * 4 + 2] = __uint_as_float(tf32cvt(qv.z));
        Qs[row * QSW + c4 * 4 + 3] = __uint_as_float(tf32cvt(qv.w));
    }
    if (tid < 64) { m_state[tid] = -1e30f; sum_state[tid] = 0.f; }

    // staging index decomposition (all 256 threads)
    const int krow = tid >> 4, kseg = tid & 15;            // K/V
    const int brow = tid >> 2, bseg = tid & 3;             // Bq
    const int trow = tid >> 3, tseg = tid & 7;             // Ts LDG

    auto stage = [&](int rc, int db) {
        float* Ks = sm + (db ? OFF_KS1 : OFF_KS0);
        float* Vr = sm + (db ? OFF_VR1 : OFF_VR0);
        __nv_bfloat16* Bq = (__nv_bfloat16*)(sm + (db ? OFF_BQ1 : OFF_BQ0));
#pragma unroll
        for (int i = 0; i < 2; i++) {
            const int row = krow + i * 16;
            cp16(&Ks[row * QSW + kseg * 4], g_k + ((size_t)bh * LL + rc + row) * DD + kseg * 4);
            cp16(&Vr[row * QSW + kseg * 4], g_v + ((size_t)bh * LL + rc + row) * DD + kseg * 4);
        }
        cp16(&Bq[brow * 40 + bseg * 8],
             g_biasq + ((size_t)bh * LL + l0 + brow) * LL + rc + bseg * 8);
        asm volatile("cp.async.commit_group;" ::: "memory");
    };
    auto ldg_ts = [&](int rc) -> uint4 {
        return *(const uint4*)(g_biaskT + ((size_t)bh * LL + rc + trow) * LL + l0 + tseg * 8);
    };

    float accpv[4][4];
#pragma unroll
    for (int i = 0; i < 4; i++)
#pragma unroll
        for (int j = 0; j < 4; j++) accpv[i][j] = 0.f;

    uint4 ts_reg = ldg_ts(0);
    stage(0, 0);

    for (int ci = 0; ci < LL / RC; ci++) {
        const int cur = ci & 1;
        float* Ks = sm + (cur ? OFF_KS1 : OFF_KS0);
        float* Vr = sm + (cur ? OFF_VR1 : OFF_VR0);
        __nv_bfloat16* Bq = (__nv_bfloat16*)(sm + (cur ? OFF_BQ1 : OFF_BQ0));
        unsigned short* TsL = (unsigned short*)(sm + OFF_TS);

        // wait for chunk `cur`, then barrier: publishes cur AND guarantees all
        // threads finished reading buffer cur^1 and Vlo/TsL of prev chunk.
        asm volatile("cp.async.wait_group 0;" ::: "memory");
        __syncthreads();

        uint4 ts_next;
        if (ci + 1 < LL / RC) {
            ts_next = ldg_ts((ci + 1) * RC);
            stage((ci + 1) * RC, cur ^ 1);
        }

        // Ts transpose store: TsL[l][r], stride 34 halfwords
        {
            const unsigned short* h = (const unsigned short*)&ts_reg;
#pragma unroll
            for (int j = 0; j < 8; j++)
                TsL[(tseg * 8 + j) * 34 + trow] = h[j];
        }
        // one-shot tf32 prep: K in place; V -> hi (in place) + lo (Vlo)
#pragma unroll
        for (int i = 0; i < 8; i++) {
            const int idx = tid + i * 256;
            const int row = idx >> 6;
            const int col = idx & 63;
            Ks[row * QSW + col] = __uint_as_float(tf32cvt(Ks[row * QSW + col]));
            const float v = Vr[row * QSW + col];
            const unsigned hv = tf32cvt(v);
            Vr[row * QSW + col]  = __uint_as_float(hv);
            Vlo[row * QSW + col] = __uint_as_float(tf32cvt(v - __uint_as_float(hv)));
        }
        __syncthreads();                    // prepped operands visible

        // ---- qk mma (clean bit loads) ----
        float accqk[2][4];
#pragma unroll
        for (int i = 0; i < 2; i++)
#pragma unroll
            for (int j = 0; j < 4; j++) accqk[i][j] = 0.f;
#pragma unroll
        for (int ks = 0; ks < 8; ks++) {
            const int kc = ks * 8 + kcl;
            unsigned a0 = __float_as_uint(Qs[arow * QSW + kc]);
            unsigned a1 = __float_as_uint(Qs[(arow + 8) * QSW + kc]);
            unsigned a2 = __float_as_uint(Qs[arow * QSW + kc + 4]);
            unsigned a3 = __float_as_uint(Qs[(arow + 8) * QSW + kc + 4]);
#pragma unroll
            for (int nt = 0; nt < 2; nt++) {
                const int nb = nh2 + nt * 8 + (lane >> 2);
                unsigned b0 = __float_as_uint(Ks[nb * QSW + kc]);
                unsigned b1 = __float_as_uint(Ks[nb * QSW + kc + 4]);
                mma_tf32(accqk[nt][0], accqk[nt][1], accqk[nt][2], accqk[nt][3],
                         a0, a1, a2, a3, b0, b1);
            }
        }
#pragma unroll
        for (int nt = 0; nt < 2; nt++) {
            const int col = nh2 + nt * 8 + 2 * (lane & 3);
#pragma unroll
            for (int half = 0; half < 2; half++) {
                const int row = arow + half * 8;
                *(float2*)&Sp[row * SPW + col] =
                    make_float2(accqk[nt][2 * half + 0], accqk[nt][2 * half + 1]);
            }
        }
        __syncthreads();                    // Sp + TsL ready

        // ---- merged stats + P (thread owns l = tid>>2, r = (tid&3)*8 .. +7) ----
        {
            const int l  = tid >> 2;
            const int c0 = (tid & 3) * 8;
            const float mv_old = m_state[l];
            float s[8];
            {
                float4 sp0 = *(float4*)&Sp[l * SPW + c0];
                float4 sp1 = *(float4*)&Sp[l * SPW + c0 + 4];
                const __nv_bfloat162* bq2 = (const __nv_bfloat162*)&Bq[l * 40 + c0];
                const __nv_bfloat162* ts2 = (const __nv_bfloat162*)&TsL[l * 34 + c0];
                float2 b0 = __bfloat1622float2(bq2[0]);
                float2 b1 = __bfloat1622float2(bq2[1]);
                float2 b2 = __bfloat1622float2(bq2[2]);
                float2 b3 = __bfloat1622float2(bq2[3]);
                float2 t0 = __bfloat1622float2(ts2[0]);
                float2 t1 = __bfloat1622float2(ts2[1]);
                float2 t2 = __bfloat1622float2(ts2[2]);
                float2 t3 = __bfloat1622float2(ts2[3]);
                s[0] = sp0.x + b0.x + t0.x;  s[1] = sp0.y + b0.y + t0.y;
                s[2] = sp0.z + b1.x + t1.x;  s[3] = sp0.w + b1.y + t1.y;
                s[4] = sp1.x + b2.x + t2.x;  s[5] = sp1.y + b2.y + t2.y;
                s[6] = sp1.z + b3.x + t3.x;  s[7] = sp1.w + b3.y + t3.y;
            }
            float mc = s[0];
#pragma unroll
            for (int j = 1; j < 8; j++) mc = fmaxf(mc, s[j]);
            mc = fmaxf(mc, __shfl_xor_sync(0xffffffffu, mc, 1));
            mc = fmaxf(mc, __shfl_xor_sync(0xffffffffu, mc, 2));
            const float mnew = fmaxf(mv_old, mc);
            float e = 0.f;
            float pv[8], ph[8];
#pragma unroll
            for (int j = 0; j < 8; j++) {
                pv[j] = __expf(s[j] - mnew);
                e += pv[j];
                ph[j] = __uint_as_float(tf32cvt(pv[j]));
            }
            float4 p0, p1, q0, q1;
            p0.x = ph[0]; p0.y = ph[1]; p0.z = ph[2]; p0.w = ph[3];
            p1.x = ph[4]; p1.y = ph[5]; p1.z = ph[6]; p1.w = ph[7];
            q0.x = __uint_as_float(tf32cvt(pv[0] - ph[0]));
            q0.y = __uint_as_float(tf32cvt(pv[1] - ph[1]));
            q0.z = __uint_as_float(tf32cvt(pv[2] - ph[2]));
            q0.w = __uint_as_float(tf32cvt(pv[3] - ph[3]));
            q1.x = __uint_as_float(tf32cvt(pv[4] - ph[4]));
            q1.y = __uint_as_float(tf32cvt(pv[5] - ph[5]));
            q1.z = __uint_as_float(tf32cvt(pv[6] - ph[6]));
            q1.w = __uint_as_float(tf32cvt(pv[7] - ph[7]));
            *(float4*)&Sp[l * SPW + c0]     = p0;
            *(float4*)&Sp[l * SPW + c0 + 4] = p1;
            *(float4*)&Pl[l * SPW + c0]     = q0;
            *(float4*)&Pl[l * SPW + c0 + 4] = q1;
            e += __shfl_xor_sync(0xffffffffu, e, 1);
            e += __shfl_xor_sync(0xffffffffu, e, 2);
            if ((tid & 3) == 0) {
                const float sc = __expf(mv_old - mnew);
                scalef[l] = sc;
                sum_state[l] = sum_state[l] * sc + e;
                m_state[l] = mnew;
            }
        }
        __syncthreads();                    // P + scalef ready

        // ---- rescale + compensated P@V mma (clean bit loads) ----
        {
            const float sc0 = scalef[arow];
            const float sc1 = scalef[arow + 8];
#pragma unroll
            for (int nt = 0; nt < 4; nt++) {
                accpv[nt][0] *= sc0; accpv[nt][1] *= sc0;
                accpv[nt][2] *= sc1; accpv[nt][3] *= sc1;
            }
        }
#pragma unroll
        for (int ks = 0; ks < 4; ks++) {
            const int kc = ks * 8 + kcl;
            unsigned ah0 = __float_as_uint(Sp[arow * SPW + kc]);
            unsigned ah1 = __float_as_uint(Sp[(arow + 8) * SPW + kc]);
            unsigned ah2 = __float_as_uint(Sp[arow * SPW + kc + 4]);
            unsigned ah3 = __float_as_uint(Sp[(arow + 8) * SPW + kc + 4]);
            unsigned al0 = __float_as_uint(Pl[arow * SPW + kc]);
            unsigned al1 = __float_as_uint(Pl[(arow + 8) * SPW + kc]);
            unsigned al2 = __float_as_uint(Pl[arow * SPW + kc + 4]);
            unsigned al3 = __float_as_uint(Pl[(arow + 8) * SPW + kc + 4]);
#pragma unroll
            for (int nt = 0; nt < 4; nt++) {
                const int nb = nhpv + nt * 8 + (lane >> 2);
                unsigned bh0 = __float_as_uint(Vr[(ks * 8 + kcl) * QSW + nb]);
                unsigned bh1 = __float_as_uint(Vr[(ks * 8 + kcl + 4) * QSW + nb]);
                unsigned bl0 = __float_as_uint(Vlo[(ks * 8 + kcl) * QSW + nb]);
                unsigned bl1 = __float_as_uint(Vlo[(ks * 8 + kcl + 4) * QSW + nb]);
                mma_tf32(accpv[nt][0], accpv[nt][1], accpv[nt][2], accpv[nt][3],
                         ah0, ah1, ah2, ah3, bh0, bh1);
                mma_tf32(accpv[nt][0], accpv[nt][1], accpv[nt][2], accpv[nt][3],
                         al0, al1, al2, al3, bh0, bh1);
                mma_tf32(accpv[nt][0], accpv[nt][1], accpv[nt][2], accpv[nt][3],
                         ah0, ah1, ah2, ah3, bl0, bl1);
            }
        }
        ts_reg = ts_next;
    }

    // ---- write out[b, l, h*64 + d] ----
    const int b_idx = bh / HH;
    const int h     = bh % HH;
#pragma unroll
    for (int half = 0; half < 2; half++) {
        const int row = arow + half * 8;
        const float inv = 1.f / sum_state[row];
        const int l = l0 + row;
#pragma unroll
        for (int nt = 0; nt < 4; nt++) {
            const int col = nhpv + nt * 8 + 2 * (lane & 3);
            float2 r;
            r.x = accpv[nt][2 * half + 0] * inv;
            r.y = accpv[nt][2 * half + 1] * inv;
            *(float2*)&out[((size_t)(b_idx * LL + l)) * HIDD + h * DD + col] = r;
        }
    }
}

// ============================================================================
// launch
// ============================================================================
extern "C" void kernel_launch(void* const* d_in, const int* in_sizes, int n_in,
                              void* d_out, int out_size)
{
    (void)in_sizes; (void)n_in; (void)out_size;
    const float* hidden = (const float*)d_in[0];
    const float* mask   = (const float*)d_in[1];
    const float* S      = (const float*)d_in[2];
    const float* Wq     = (const float*)d_in[3];
    const float* bq     = (const float*)d_in[4];
    const float* Wk     = (const float*)d_in[5];
    const float* bk     = (const float*)d_in[6];
    const float* Wv     = (const float*)d_in[7];
    const float* bv     = (const float*)d_in[8];
    float* out = (float*)d_out;

    static int smem_set = 0;
    if (!smem_set) {
        cudaFuncSetAttribute(fused_attn_kernel,
                             cudaFuncAttributeMaxDynamicSharedMemorySize,
                             SMEM_FLOATS * (int)sizeof(float));
        cudaFuncSetAttribute(bias_stream_kernel,
                             cudaFuncAttributeMaxDynamicSharedMemorySize,
                             BIAS_SMEM_FLOATS * (int)sizeof(float));
        smem_set = 1;
    }

    dim3 g1(64, 12, 3);
    qkv_mma_kernel<<<g1, 256>>>(hidden, Wq, bq, Wk, bk, Wv, bv);

    dim3 g2(1024, 2);                        // (f, variant)
    bias_stream_kernel<<<g2, 256, BIAS_SMEM_FLOATS * sizeof(float)>>>(S, mask);

    dim3 g3(16, 48);
    fused_attn_kernel<<<g3, 256, SMEM_FLOATS * sizeof(float)>>>(out);
}

// round 8
// speedup vs baseline: 1.0415x; 1.0415x over previous
#include <cuda_runtime.h>
#include <cuda_bf16.h>
#include <math.h>

#define BB   4
#define LL   1024
#define HIDD 768
#define HH   12
#define DD   64
#define BH   (BB*HH)

// ---- scratch (device globals; no allocation allowed) ----
__device__ float g_q[BH * LL * DD];                        // [bh, l, d] (pre-scaled 0.125)
__device__ float g_k[BH * LL * DD];                        // [bh, l, d]
__device__ float g_v[BH * LL * DD];                        // [bh, l, d]
__device__ __nv_bfloat16 g_biasq[(size_t)BH * LL * LL];    // [bh, l, r] = qS/8 + mask
__device__ __nv_bfloat16 g_biaskT[(size_t)BH * LL * LL];   // [bh, r, l] = kS/8

// ---------------- helpers ----------------
__device__ __forceinline__ unsigned tf32cvt(float x) {
    unsigned u;
    asm("cvt.rna.tf32.f32 %0, %1;" : "=r"(u) : "f"(x));
    return u;
}
__device__ __forceinline__ void mma_tf32(float& c0, float& c1, float& c2, float& c3,
                                         unsigned a0, unsigned a1, unsigned a2, unsigned a3,
                                         unsigned b0, unsigned b1) {
    asm("mma.sync.aligned.m16n8k8.row.col.f32.tf32.tf32.f32 "
        "{%0,%1,%2,%3},{%4,%5,%6,%7},{%8,%9},{%0,%1,%2,%3};"
        : "+f"(c0), "+f"(c1), "+f"(c2), "+f"(c3)
        : "r"(a0), "r"(a1), "r"(a2), "r"(a3), "r"(b0), "r"(b1));
}
__device__ __forceinline__ void cp16(const void* smem_dst, const void* gsrc) {
    unsigned sa = (unsigned)__cvta_generic_to_shared(smem_dst);
    asm volatile("cp.async.cg.shared.global [%0], [%1], 16;" :: "r"(sa), "l"(gsrc));
}

// ============================================================================
// K1: QKV projection, tf32 mma, register double-buffered gmem staging.
// blockIdx.z selects q/k/v.  Block tile: M=64 x N=64, K chunks of 64.
// ============================================================================
__global__ __launch_bounds__(256) void qkv_mma_kernel(
    const float* __restrict__ X,
    const float* __restrict__ Wq, const float* __restrict__ bq,
    const float* __restrict__ Wk, const float* __restrict__ bk,
    const float* __restrict__ Wv, const float* __restrict__ bv)
{
    __shared__ unsigned Xs[64][68];
    __shared__ unsigned Ws[64][68];

    const int which = blockIdx.z;
    const float* W    = (which == 0) ? Wq : (which == 1) ? Wk : Wv;
    const float* bias = (which == 0) ? bq : (which == 1) ? bk : bv;

    const int tid  = threadIdx.x;
    const int warp = tid >> 5;
    const int lane = tid & 31;
    const int m0 = blockIdx.x * 64;
    const int n0 = blockIdx.y * 64;
    const int mstrip = (warp & 3) * 16;
    const int nh     = (warp >> 2) * 32;

    float acc[4][4];
#pragma unroll
    for (int i = 0; i < 4; i++)
#pragma unroll
        for (int j = 0; j < 4; j++) acc[i][j] = 0.f;

    // register prefetch buffers (4 stage iterations x (X,W))
    float4 xr[4], wr[4];
#pragma unroll
    for (int i = 0; i < 4; i++) {
        const int idx = tid + i * 256;
        const int row = idx >> 4;
        const int c4  = idx & 15;
        xr[i] = *(const float4*)(X + (size_t)(m0 + row) * HIDD + c4 * 4);
        wr[i] = *(const float4*)(W + (size_t)(n0 + row) * HIDD + c4 * 4);
    }

    for (int k0 = 0; k0 < HIDD; k0 += 64) {
        __syncthreads();
#pragma unroll
        for (int i = 0; i < 4; i++) {
            const int idx = tid + i * 256;
            const int row = idx >> 4;
            const int c4  = idx & 15;
            Xs[row][c4 * 4 + 0] = tf32cvt(xr[i].x); Xs[row][c4 * 4 + 1] = tf32cvt(xr[i].y);
            Xs[row][c4 * 4 + 2] = tf32cvt(xr[i].z); Xs[row][c4 * 4 + 3] = tf32cvt(xr[i].w);
            Ws[row][c4 * 4 + 0] = tf32cvt(wr[i].x); Ws[row][c4 * 4 + 1] = tf32cvt(wr[i].y);
            Ws[row][c4 * 4 + 2] = tf32cvt(wr[i].z); Ws[row][c4 * 4 + 3] = tf32cvt(wr[i].w);
        }
        __syncthreads();
        if (k0 + 64 < HIDD) {
#pragma unroll
            for (int i = 0; i < 4; i++) {
                const int idx = tid + i * 256;
                const int row = idx >> 4;
                const int c4  = idx & 15;
                xr[i] = *(const float4*)(X + (size_t)(m0 + row) * HIDD + k0 + 64 + c4 * 4);
                wr[i] = *(const float4*)(W + (size_t)(n0 + row) * HIDD + k0 + 64 + c4 * 4);
            }
        }
#pragma unroll
        for (int ks = 0; ks < 8; ks++) {
            const int kc = ks * 8 + (lane & 3);
            unsigned a0 = Xs[mstrip + (lane >> 2)][kc];
            unsigned a1 = Xs[mstrip + (lane >> 2) + 8][kc];
            unsigned a2 = Xs[mstrip + (lane >> 2)][kc + 4];
            unsigned a3 = Xs[mstrip + (lane >> 2) + 8][kc + 4];
#pragma unroll
            for (int nt = 0; nt < 4; nt++) {
                const int nb = nh + nt * 8;
                unsigned b0 = Ws[nb + (lane >> 2)][kc];
                unsigned b1 = Ws[nb + (lane >> 2)][kc + 4];
                mma_tf32(acc[nt][0], acc[nt][1], acc[nt][2], acc[nt][3],
                         a0, a1, a2, a3, b0, b1);
            }
        }
    }

    float* out = (which == 0) ? g_q : (which == 1) ? g_k : g_v;
    const float scale = (which == 0) ? 0.125f : 1.0f;
    const int row0 = m0 + mstrip + (lane >> 2);
#pragma unroll
    for (int nt = 0; nt < 4; nt++) {
        const int col = n0 + nh + nt * 8 + 2 * (lane & 3);
        const int h = col >> 6;
        const int d = col & 63;
#pragma unroll
        for (int half = 0; half < 2; half++) {
            const int row = row0 + half * 8;
            const int b_idx = row >> 10;
            const int l     = row & (LL - 1);
            float2 r;
            r.x = (acc[nt][2 * half + 0] + bias[col + 0]) * scale;
            r.y = (acc[nt][2 * half + 1] + bias[col + 1]) * scale;
            *(float2*)&out[(((size_t)b_idx * HH + h) * LL + l) * DD + d] = r;
        }
    }
}

// ============================================================================
// K2: structure-bias GEMMs (bf16 output) — round-6 proven version.
//  variant 0 (f=l): g_biasq[bh, f, n]  = q[bh,f,:].S[f,n,:] + mask[b,n]
//  variant 1 (f=r): g_biaskT[bh, f, n] = 0.125 * k[bh,f,:].S[n,f,:]
// ============================================================================
__global__ __launch_bounds__(256) void bias_mma_kernel(
    const float* __restrict__ S, const float* __restrict__ mask, int variant)
{
    __shared__ unsigned As[64][68];
    __shared__ unsigned Ss[64][68];

    const int tid  = threadIdx.x;
    const int warp = tid >> 5;
    const int lane = tid & 31;
    const int n0 = blockIdx.x * 64;
    const int f  = blockIdx.y;
    const int mstrip = (warp & 3) * 16;
    const int nh     = (warp >> 2) * 32;

    const float* Aop = (variant == 0) ? g_q : g_k;

#pragma unroll
    for (int i = 0; i < 4; i++) {
        const int idx = tid + i * 256;
        const int row = idx >> 4;
        const int c4  = idx & 15;
        if (row < BH) {
            float4 av = *(const float4*)(Aop + ((size_t)row * LL + f) * DD + c4 * 4);
            As[row][c4 * 4 + 0] = tf32cvt(av.x); As[row][c4 * 4 + 1] = tf32cvt(av.y);
            As[row][c4 * 4 + 2] = tf32cvt(av.z); As[row][c4 * 4 + 3] = tf32cvt(av.w);
        } else {
            As[row][c4 * 4 + 0] = 0u; As[row][c4 * 4 + 1] = 0u;
            As[row][c4 * 4 + 2] = 0u; As[row][c4 * 4 + 3] = 0u;
        }
        size_t soff = (variant == 0)
            ? (((size_t)f * LL + n0 + row) * DD + c4 * 4)
            : (((size_t)(n0 + row) * LL + f) * DD + c4 * 4);
        float4 sv = *(const float4*)(S + soff);
        Ss[row][c4 * 4 + 0] = tf32cvt(sv.x); Ss[row][c4 * 4 + 1] = tf32cvt(sv.y);
        Ss[row][c4 * 4 + 2] = tf32cvt(sv.z); Ss[row][c4 * 4 + 3] = tf32cvt(sv.w);
    }
    __syncthreads();

    float acc[4][4];
#pragma unroll
    for (int i = 0; i < 4; i++)
#pragma unroll
        for (int j = 0; j < 4; j++) acc[i][j] = 0.f;

#pragma unroll
    for (int ks = 0; ks < 8; ks++) {
        const int kc = ks * 8 + (lane & 3);
        unsigned a0 = As[mstrip + (lane >> 2)][kc];
        unsigned a1 = As[mstrip + (lane >> 2) + 8][kc];
        unsigned a2 = As[mstrip + (lane >> 2)][kc + 4];
        unsigned a3 = As[mstrip + (lane >> 2) + 8][kc + 4];
#pragma unroll
        for (int nt = 0; nt < 4; nt++) {
            const int nb = nh + nt * 8;
            unsigned b0 = Ss[nb + (lane >> 2)][kc];
            unsigned b1 = Ss[nb + (lane >> 2)][kc + 4];
            mma_tf32(acc[nt][0], acc[nt][1], acc[nt][2], acc[nt][3],
                     a0, a1, a2, a3, b0, b1);
        }
    }

    const int row0 = mstrip + (lane >> 2);   // bh index
#pragma unroll
    for (int nt = 0; nt < 4; nt++) {
        const int col = n0 + nh + nt * 8 + 2 * (lane & 3);
#pragma unroll
        for (int half = 0; half < 2; half++) {
            const int bh = row0 + half * 8;
            if (bh >= BH) continue;
            if (variant == 0) {
                const int b_idx = bh / HH;
                __nv_bfloat162 bv = __floats2bfloat162_rn(
                    acc[nt][2 * half + 0] + mask[b_idx * LL + col + 0],
                    acc[nt][2 * half + 1] + mask[b_idx * LL + col + 1]);
                *(__nv_bfloat162*)&g_biasq[((size_t)bh * LL + f) * LL + col] = bv;
            } else {
                __nv_bfloat162 bv = __floats2bfloat162_rn(
                    acc[nt][2 * half + 0] * 0.125f,
                    acc[nt][2 * half + 1] * 0.125f);
                *(__nv_bfloat162*)&g_biaskT[((size_t)bh * LL + f) * LL + col] = bv;
            }
        }
    }
}

// ============================================================================
// K3: fused flash attention, cp.async double-buffered, per-chunk tf32
// pre-conversion (K in place, V split hi/lo).  P@V compensated (3 mmas).
// ============================================================================
#define RC      32
#define SPW     36
#define QSW     68

// smem layout (float units)
#define OFF_QS    0                       // 64*68 = 4352
#define OFF_KS0   4352                    // 32*68 = 2176
#define OFF_KS1   6528
#define OFF_VR0   8704
#define OFF_VR1   10880
#define OFF_VLO   13056                   // 32*68 = 2176
#define OFF_SP    15232                   // 64*36 = 2304
#define OFF_PL    17536
#define OFF_BQ0   19840                   // 64*40 bf16 = 1280 floats
#define OFF_BQ1   21120
#define OFF_TS    22400                   // 64*34 bf16 = 1088 floats
#define OFF_MS    23488
#define OFF_SU    23552
#define OFF_SC    23616
#define SMEM_FLOATS 23680                 // 94720 B

__global__ __launch_bounds__(256) void fused_attn_kernel(float* __restrict__ out)
{
    extern __shared__ float sm[];
    float* Qs  = sm + OFF_QS;
    float* Vlo = sm + OFF_VLO;
    float* Sp  = sm + OFF_SP;
    float* Pl  = sm + OFF_PL;
    float* m_state   = sm + OFF_MS;
    float* sum_state = sm + OFF_SU;
    float* scalef    = sm + OFF_SC;

    const int tid  = threadIdx.x;
    const int warp = tid >> 5;
    const int lane = tid & 31;
    const int bh   = blockIdx.y;
    const int l0   = blockIdx.x * 64;

    const int mstrip = (warp & 3) * 16;
    const int nh2    = (warp >> 2) * 16;   // qk N = 32
    const int nhpv   = (warp >> 2) * 32;   // pv N = 64
    const int arow   = mstrip + (lane >> 2);
    const int kcl    = lane & 3;

    // ---- prologue: Q tile -> tf32 smem ----
#pragma unroll
    for (int i = 0; i < 4; i++) {
        const int idx = tid + i * 256;
        const int row = idx >> 4;
        const int c4  = idx & 15;
        float4 qv = *(const float4*)(g_q + ((size_t)bh * LL + l0 + row) * DD + c4 * 4);
        Qs[row * QSW + c4 * 4 + 0] = __uint_as_float(tf32cvt(qv.x));
        Qs[row * QSW + c4 * 4 + 1] = __uint_as_float(tf32cvt(qv.y));
        Qs[row * QSW + c4 * 4 + 2] = __uint_as_float(tf32cvt(qv.z));
        Qs[row * QSW + c4 * 4 + 3] = __uint_as_float(tf32cvt(qv.w));
    }
    if (tid < 64) { m_state[tid] = -1e30f; sum_state[tid] = 0.f; }

    // staging index decomposition (all 256 threads)
    const int krow = tid >> 4, kseg = tid & 15;            // K/V
    const int brow = tid >> 2, bseg = tid & 3;             // Bq
    const int trow = tid >> 3, tseg = tid & 7;             // Ts LDG

    auto stage = [&](int rc, int db) {
        float* Ks = sm + (db ? OFF_KS1 : OFF_KS0);
        float* Vr = sm + (db ? OFF_VR1 : OFF_VR0);
        __nv_bfloat16* Bq = (__nv_bfloat16*)(sm + (db ? OFF_BQ1 : OFF_BQ0));
#pragma unroll
        for (int i = 0; i < 2; i++) {
            const int row = krow + i * 16;
            cp16(&Ks[row * QSW + kseg * 4], g_k + ((size_t)bh * LL + rc + row) * DD + kseg * 4);
            cp16(&Vr[row * QSW + kseg * 4], g_v + ((size_t)bh * LL + rc + row) * DD + kseg * 4);
        }
        cp16(&Bq[brow * 40 + bseg * 8],
             g_biasq + ((size_t)bh * LL + l0 + brow) * LL + rc + bseg * 8);
        asm volatile("cp.async.commit_group;" ::: "memory");
    };
    auto ldg_ts = [&](int rc) -> uint4 {
        return *(const uint4*)(g_biaskT + ((size_t)bh * LL + rc + trow) * LL + l0 + tseg * 8);
    };

    float accpv[4][4];
#pragma unroll
    for (int i = 0; i < 4; i++)
#pragma unroll
        for (int j = 0; j < 4; j++) accpv[i][j] = 0.f;

    uint4 ts_reg = ldg_ts(0);
    stage(0, 0);

    for (int ci = 0; ci < LL / RC; ci++) {
        const int cur = ci & 1;
        float* Ks = sm + (cur ? OFF_KS1 : OFF_KS0);
        float* Vr = sm + (cur ? OFF_VR1 : OFF_VR0);
        __nv_bfloat16* Bq = (__nv_bfloat16*)(sm + (cur ? OFF_BQ1 : OFF_BQ0));
        unsigned short* TsL = (unsigned short*)(sm + OFF_TS);

        asm volatile("cp.async.wait_group 0;" ::: "memory");
        __syncthreads();

        uint4 ts_next;
        if (ci + 1 < LL / RC) {
            ts_next = ldg_ts((ci + 1) * RC);
            stage((ci + 1) * RC, cur ^ 1);
        }

        // Ts transpose store: TsL[l][r], stride 34 halfwords
        {
            const unsigned short* h = (const unsigned short*)&ts_reg;
#pragma unroll
            for (int j = 0; j < 8; j++)
                TsL[(tseg * 8 + j) * 34 + trow] = h[j];
        }
        // one-shot tf32 prep: K in place; V -> hi (in place) + lo (Vlo)
#pragma unroll
        for (int i = 0; i < 8; i++) {
            const int idx = tid + i * 256;
            const int row = idx >> 6;
            const int col = idx & 63;
            Ks[row * QSW + col] = __uint_as_float(tf32cvt(Ks[row * QSW + col]));
            const float v = Vr[row * QSW + col];
            const unsigned hv = tf32cvt(v);
            Vr[row * QSW + col]  = __uint_as_float(hv);
            Vlo[row * QSW + col] = __uint_as_float(tf32cvt(v - __uint_as_float(hv)));
        }
        __syncthreads();                    // prepped operands visible

        // ---- qk mma (clean bit loads) ----
        float accqk[2][4];
#pragma unroll
        for (int i = 0; i < 2; i++)
#pragma unroll
            for (int j = 0; j < 4; j++) accqk[i][j] = 0.f;
#pragma unroll
        for (int ks = 0; ks < 8; ks++) {
            const int kc = ks * 8 + kcl;
            unsigned a0 = __float_as_uint(Qs[arow * QSW + kc]);
            unsigned a1 = __float_as_uint(Qs[(arow + 8) * QSW + kc]);
            unsigned a2 = __float_as_uint(Qs[arow * QSW + kc + 4]);
            unsigned a3 = __float_as_uint(Qs[(arow + 8) * QSW + kc + 4]);
#pragma unroll
            for (int nt = 0; nt < 2; nt++) {
                const int nb = nh2 + nt * 8 + (lane >> 2);
                unsigned b0 = __float_as_uint(Ks[nb * QSW + kc]);
                unsigned b1 = __float_as_uint(Ks[nb * QSW + kc + 4]);
                mma_tf32(accqk[nt][0], accqk[nt][1], accqk[nt][2], accqk[nt][3],
                         a0, a1, a2, a3, b0, b1);
            }
        }
#pragma unroll
        for (int nt = 0; nt < 2; nt++) {
            const int col = nh2 + nt * 8 + 2 * (lane & 3);
#pragma unroll
            for (int half = 0; half < 2; half++) {
                const int row = arow + half * 8;
                *(float2*)&Sp[row * SPW + col] =
                    make_float2(accqk[nt][2 * half + 0], accqk[nt][2 * half + 1]);
            }
        }
        __syncthreads();                    // Sp + TsL ready

        // ---- merged stats + P ----
        {
            const int l  = tid >> 2;
            const int c0 = (tid & 3) * 8;
            const float mv_old = m_state[l];
            float s[8];
            {
                float4 sp0 = *(float4*)&Sp[l * SPW + c0];
                float4 sp1 = *(float4*)&Sp[l * SPW + c0 + 4];
                const __nv_bfloat162* bq2 = (const __nv_bfloat162*)&Bq[l * 40 + c0];
                const __nv_bfloat162* ts2 = (const __nv_bfloat162*)&TsL[l * 34 + c0];
                float2 b0 = __bfloat1622float2(bq2[0]);
                float2 b1 = __bfloat1622float2(bq2[1]);
                float2 b2 = __bfloat1622float2(bq2[2]);
                float2 b3 = __bfloat1622float2(bq2[3]);
                float2 t0 = __bfloat1622float2(ts2[0]);
                float2 t1 = __bfloat1622float2(ts2[1]);
                float2 t2 = __bfloat1622float2(ts2[2]);
                float2 t3 = __bfloat1622float2(ts2[3]);
                s[0] = sp0.x + b0.x + t0.x;  s[1] = sp0.y + b0.y + t0.y;
                s[2] = sp0.z + b1.x + t1.x;  s[3] = sp0.w + b1.y + t1.y;
                s[4] = sp1.x + b2.x + t2.x;  s[5] = sp1.y + b2.y + t2.y;
                s[6] = sp1.z + b3.x + t3.x;  s[7] = sp1.w + b3.y + t3.y;
            }
            float mc = s[0];
#pragma unroll
            for (int j = 1; j < 8; j++) mc = fmaxf(mc, s[j]);
            mc = fmaxf(mc, __shfl_xor_sync(0xffffffffu, mc, 1));
            mc = fmaxf(mc, __shfl_xor_sync(0xffffffffu, mc, 2));
            const float mnew = fmaxf(mv_old, mc);
            float e = 0.f;
            float pv[8], ph[8];
#pragma unroll
            for (int j = 0; j < 8; j++) {
                pv[j] = __expf(s[j] - mnew);
                e += pv[j];
                ph[j] = __uint_as_float(tf32cvt(pv[j]));
            }
            float4 p0, p1, q0, q1;
            p0.x = ph[0]; p0.y = ph[1]; p0.z = ph[2]; p0.w = ph[3];
            p1.x = ph[4]; p1.y = ph[5]; p1.z = ph[6]; p1.w = ph[7];
            q0.x = __uint_as_float(tf32cvt(pv[0] - ph[0]));
            q0.y = __uint_as_float(tf32cvt(pv[1] - ph[1]));
            q0.z = __uint_as_float(tf32cvt(pv[2] - ph[2]));
            q0.w = __uint_as_float(tf32cvt(pv[3] - ph[3]));
            q1.x = __uint_as_float(tf32cvt(pv[4] - ph[4]));
            q1.y = __uint_as_float(tf32cvt(pv[5] - ph[5]));
            q1.z = __uint_as_float(tf32cvt(pv[6] - ph[6]));
            q1.w = __uint_as_float(tf32cvt(pv[7] - ph[7]));
            *(float4*)&Sp[l * SPW + c0]     = p0;
            *(float4*)&Sp[l * SPW + c0 + 4] = p1;
            *(float4*)&Pl[l * SPW + c0]     = q0;
            *(float4*)&Pl[l * SPW + c0 + 4] = q1;
            e += __shfl_xor_sync(0xffffffffu, e, 1);
            e += __shfl_xor_sync(0xffffffffu, e, 2);
            if ((tid & 3) == 0) {
                const float sc = __expf(mv_old - mnew);
                scalef[l] = sc;
                sum_state[l] = sum_state[l] * sc + e;
                m_state[l] = mnew;
            }
        }
        __syncthreads();                    // P + scalef ready

        // ---- rescale + compensated P@V mma (clean bit loads) ----
        {
            const float sc0 = scalef[arow];
            const float sc1 = scalef[arow + 8];
#pragma unroll
            for (int nt = 0; nt < 4; nt++) {
                accpv[nt][0] *= sc0; accpv[nt][1] *= sc0;
                accpv[nt][2] *= sc1; accpv[nt][3] *= sc1;
            }
        }
#pragma unroll
        for (int ks = 0; ks < 4; ks++) {
            const int kc = ks * 8 + kcl;
            unsigned ah0 = __float_as_uint(Sp[arow * SPW + kc]);
            unsigned ah1 = __float_as_uint(Sp[(arow + 8) * SPW + kc]);
            unsigned ah2 = __float_as_uint(Sp[arow * SPW + kc + 4]);
            unsigned ah3 = __float_as_uint(Sp[(arow + 8) * SPW + kc + 4]);
            unsigned al0 = __float_as_uint(Pl[arow * SPW + kc]);
            unsigned al1 = __float_as_uint(Pl[(arow + 8) * SPW + kc]);
            unsigned al2 = __float_as_uint(Pl[arow * SPW + kc + 4]);
            unsigned al3 = __float_as_uint(Pl[(arow + 8) * SPW + kc + 4]);
#pragma unroll
            for (int nt = 0; nt < 4; nt++) {
                const int nb = nhpv + nt * 8 + (lane >> 2);
                unsigned bh0 = __float_as_uint(Vr[(ks * 8 + kcl) * QSW + nb]);
                unsigned bh1 = __float_as_uint(Vr[(ks * 8 + kcl + 4) * QSW + nb]);
                unsigned bl0 = __float_as_uint(Vlo[(ks * 8 + kcl) * QSW + nb]);
                unsigned bl1 = __float_as_uint(Vlo[(ks * 8 + kcl + 4) * QSW + nb]);
                mma_tf32(accpv[nt][0], accpv[nt][1], accpv[nt][2], accpv[nt][3],
                         ah0, ah1, ah2, ah3, bh0, bh1);
                mma_tf32(accpv[nt][0], accpv[nt][1], accpv[nt][2], accpv[nt][3],
                         al0, al1, al2, al3, bh0, bh1);
                mma_tf32(accpv[nt][0], accpv[nt][1], accpv[nt][2], accpv[nt][3],
                         ah0, ah1, ah2, ah3, bl0, bl1);
            }
        }
        ts_reg = ts_next;
    }

    // ---- write out[b, l, h*64 + d] ----
    const int b_idx = bh / HH;
    const int h     = bh % HH;
#pragma unroll
    for (int half = 0; half < 2; half++) {
        const int row = arow + half * 8;
        const float inv = 1.f / sum_state[row];
        const int l = l0 + row;
#pragma unroll
        for (int nt = 0; nt < 4; nt++) {
            const int col = nhpv + nt * 8 + 2 * (lane & 3);
            float2 r;
            r.x = accpv[nt][2 * half + 0] * inv;
            r.y = accpv[nt][2 * half + 1] * inv;
            *(float2*)&out[((size_t)(b_idx * LL + l)) * HIDD + h * DD + col] = r;
        }
    }
}

// ============================================================================
// launch
// ============================================================================
extern "C" void kernel_launch(void* const* d_in, const int* in_sizes, int n_in,
                              void* d_out, int out_size)
{
    (void)in_sizes; (void)n_in; (void)out_size;
    const float* hidden = (const float*)d_in[0];
    const float* mask   = (const float*)d_in[1];
    const float* S      = (const float*)d_in[2];
    const float* Wq     = (const float*)d_in[3];
    const float* bq     = (const float*)d_in[4];
    const float* Wk     = (const float*)d_in[5];
    const float* bk     = (const float*)d_in[6];
    const float* Wv     = (const float*)d_in[7];
    const float* bv     = (const float*)d_in[8];
    float* out = (float*)d_out;

    static int smem_set = 0;
    if (!smem_set) {
        cudaFuncSetAttribute(fused_attn_kernel,
                             cudaFuncAttributeMaxDynamicSharedMemorySize,
                             SMEM_FLOATS * (int)sizeof(float));
        smem_set = 1;
    }

    dim3 g1(64, 12, 3);
    qkv_mma_kernel<<<g1, 256>>>(hidden, Wq, bq, Wk, bk, Wv, bv);

    dim3 g2(16, 1024);
    bias_mma_kernel<<<g2, 256>>>(S, mask, 0);   // q-side -> g_biasq (bf16, +mask)
    bias_mma_kernel<<<g2, 256>>>(S, mask, 1);   // k-side -> g_biaskT (bf16)

    dim3 g3(16, 48);
    fused_attn_kernel<<<g3, 256, SMEM_FLOATS * sizeof(float)>>>(out);
}

// round 9
// speedup vs baseline: 1.0940x; 1.0504x over previous
#include <cuda_runtime.h>
#include <cuda_bf16.h>
#include <math.h>

#define BB   4
#define LL   1024
#define HIDD 768
#define HH   12
#define DD   64
#define BH   (BB*HH)

// ---- scratch (device globals; no allocation allowed) ----
__device__ float g_q[BH * LL * DD];                        // [bh, l, d] tf32 bits (pre-scaled 0.125)
__device__ float g_k[BH * LL * DD];                        // [bh, l, d] tf32 bits
__device__ float g_v[BH * LL * DD];                        // [bh, l, d] tf32 hi bits
__device__ float g_vl[BH * LL * DD];                       // [bh, l, d] tf32 lo bits
__device__ __nv_bfloat16 g_biasq[(size_t)BH * LL * LL];    // [bh, l, r] = qS/8 + mask
__device__ __nv_bfloat16 g_biaskT[(size_t)BH * LL * LL];   // [bh, r, l] = kS/8

// ---------------- helpers ----------------
__device__ __forceinline__ unsigned tf32cvt(float x) {
    unsigned u;
    asm("cvt.rna.tf32.f32 %0, %1;" : "=r"(u) : "f"(x));
    return u;
}
__device__ __forceinline__ void mma_tf32(float& c0, float& c1, float& c2, float& c3,
                                         unsigned a0, unsigned a1, unsigned a2, unsigned a3,
                                         unsigned b0, unsigned b1) {
    asm("mma.sync.aligned.m16n8k8.row.col.f32.tf32.tf32.f32 "
        "{%0,%1,%2,%3},{%4,%5,%6,%7},{%8,%9},{%0,%1,%2,%3};"
        : "+f"(c0), "+f"(c1), "+f"(c2), "+f"(c3)
        : "r"(a0), "r"(a1), "r"(a2), "r"(a3), "r"(b0), "r"(b1));
}
__device__ __forceinline__ void cp16(const void* smem_dst, const void* gsrc) {
    unsigned sa = (unsigned)__cvta_generic_to_shared(smem_dst);
    asm volatile("cp.async.cg.shared.global [%0], [%1], 16;" :: "r"(sa), "l"(gsrc));
}

// ============================================================================
// K1: QKV projection, tf32 mma, register double-buffered staging.
// q/k stored as tf32-bit floats; v stored as tf32 hi/lo pair.
// ============================================================================
__global__ __launch_bounds__(256) void qkv_mma_kernel(
    const float* __restrict__ X,
    const float* __restrict__ Wq, const float* __restrict__ bq,
    const float* __restrict__ Wk, const float* __restrict__ bk,
    const float* __restrict__ Wv, const float* __restrict__ bv)
{
    __shared__ unsigned Xs[64][68];
    __shared__ unsigned Ws[64][68];

    const int which = blockIdx.z;
    const float* W    = (which == 0) ? Wq : (which == 1) ? Wk : Wv;
    const float* bias = (which == 0) ? bq : (which == 1) ? bk : bv;

    const int tid  = threadIdx.x;
    const int warp = tid >> 5;
    const int lane = tid & 31;
    const int m0 = blockIdx.x * 64;
    const int n0 = blockIdx.y * 64;
    const int mstrip = (warp & 3) * 16;
    const int nh     = (warp >> 2) * 32;

    float acc[4][4];
#pragma unroll
    for (int i = 0; i < 4; i++)
#pragma unroll
        for (int j = 0; j < 4; j++) acc[i][j] = 0.f;

    float4 xr[4], wr[4];
#pragma unroll
    for (int i = 0; i < 4; i++) {
        const int idx = tid + i * 256;
        const int row = idx >> 4;
        const int c4  = idx & 15;
        xr[i] = *(const float4*)(X + (size_t)(m0 + row) * HIDD + c4 * 4);
        wr[i] = *(const float4*)(W + (size_t)(n0 + row) * HIDD + c4 * 4);
    }

    for (int k0 = 0; k0 < HIDD; k0 += 64) {
        __syncthreads();
#pragma unroll
        for (int i = 0; i < 4; i++) {
            const int idx = tid + i * 256;
            const int row = idx >> 4;
            const int c4  = idx & 15;
            Xs[row][c4 * 4 + 0] = tf32cvt(xr[i].x); Xs[row][c4 * 4 + 1] = tf32cvt(xr[i].y);
            Xs[row][c4 * 4 + 2] = tf32cvt(xr[i].z); Xs[row][c4 * 4 + 3] = tf32cvt(xr[i].w);
            Ws[row][c4 * 4 + 0] = tf32cvt(wr[i].x); Ws[row][c4 * 4 + 1] = tf32cvt(wr[i].y);
            Ws[row][c4 * 4 + 2] = tf32cvt(wr[i].z); Ws[row][c4 * 4 + 3] = tf32cvt(wr[i].w);
        }
        __syncthreads();
        if (k0 + 64 < HIDD) {
#pragma unroll
            for (int i = 0; i < 4; i++) {
                const int idx = tid + i * 256;
                const int row = idx >> 4;
                const int c4  = idx & 15;
                xr[i] = *(const float4*)(X + (size_t)(m0 + row) * HIDD + k0 + 64 + c4 * 4);
                wr[i] = *(const float4*)(W + (size_t)(n0 + row) * HIDD + k0 + 64 + c4 * 4);
            }
        }
#pragma unroll
        for (int ks = 0; ks < 8; ks++) {
            const int kc = ks * 8 + (lane & 3);
            unsigned a0 = Xs[mstrip + (lane >> 2)][kc];
            unsigned a1 = Xs[mstrip + (lane >> 2) + 8][kc];
            unsigned a2 = Xs[mstrip + (lane >> 2)][kc + 4];
            unsigned a3 = Xs[mstrip + (lane >> 2) + 8][kc + 4];
#pragma unroll
            for (int nt = 0; nt < 4; nt++) {
                const int nb = nh + nt * 8;
                unsigned b0 = Ws[nb + (lane >> 2)][kc];
                unsigned b1 = Ws[nb + (lane >> 2)][kc + 4];
                mma_tf32(acc[nt][0], acc[nt][1], acc[nt][2], acc[nt][3],
                         a0, a1, a2, a3, b0, b1);
            }
        }
    }

    const float scale = (which == 0) ? 0.125f : 1.0f;
    const int row0 = m0 + mstrip + (lane >> 2);
#pragma unroll
    for (int nt = 0; nt < 4; nt++) {
        const int col = n0 + nh + nt * 8 + 2 * (lane & 3);
        const int h = col >> 6;
        const int d = col & 63;
#pragma unroll
        for (int half = 0; half < 2; half++) {
            const int row = row0 + half * 8;
            const int b_idx = row >> 10;
            const int l     = row & (LL - 1);
            const size_t off = (((size_t)b_idx * HH + h) * LL + l) * DD + d;
            const float y0 = (acc[nt][2 * half + 0] + bias[col + 0]) * scale;
            const float y1 = (acc[nt][2 * half + 1] + bias[col + 1]) * scale;
            if (which == 2) {
                float2 rh, rl;
                rh.x = __uint_as_float(tf32cvt(y0));
                rh.y = __uint_as_float(tf32cvt(y1));
                rl.x = __uint_as_float(tf32cvt(y0 - rh.x));
                rl.y = __uint_as_float(tf32cvt(y1 - rh.y));
                *(float2*)&g_v[off]  = rh;
                *(float2*)&g_vl[off] = rl;
            } else {
                float* out = (which == 0) ? g_q : g_k;
                float2 r;
                r.x = __uint_as_float(tf32cvt(y0));
                r.y = __uint_as_float(tf32cvt(y1));
                *(float2*)&out[off] = r;
            }
        }
    }
}

// ============================================================================
// K2: structure-bias GEMMs (bf16 output) — round-6 proven version.
// g_q/g_k already hold tf32-bit floats (cvt here is idempotent).
// ============================================================================
__global__ __launch_bounds__(256) void bias_mma_kernel(
    const float* __restrict__ S, const float* __restrict__ mask, int variant)
{
    __shared__ unsigned As[64][68];
    __shared__ unsigned Ss[64][68];

    const int tid  = threadIdx.x;
    const int warp = tid >> 5;
    const int lane = tid & 31;
    const int n0 = blockIdx.x * 64;
    const int f  = blockIdx.y;
    const int mstrip = (warp & 3) * 16;
    const int nh     = (warp >> 2) * 32;

    const float* Aop = (variant == 0) ? g_q : g_k;

#pragma unroll
    for (int i = 0; i < 4; i++) {
        const int idx = tid + i * 256;
        const int row = idx >> 4;
        const int c4  = idx & 15;
        if (row < BH) {
            float4 av = *(const float4*)(Aop + ((size_t)row * LL + f) * DD + c4 * 4);
            As[row][c4 * 4 + 0] = __float_as_uint(av.x);
            As[row][c4 * 4 + 1] = __float_as_uint(av.y);
            As[row][c4 * 4 + 2] = __float_as_uint(av.z);
            As[row][c4 * 4 + 3] = __float_as_uint(av.w);
        } else {
            As[row][c4 * 4 + 0] = 0u; As[row][c4 * 4 + 1] = 0u;
            As[row][c4 * 4 + 2] = 0u; As[row][c4 * 4 + 3] = 0u;
        }
        size_t soff = (variant == 0)
            ? (((size_t)f * LL + n0 + row) * DD + c4 * 4)
            : (((size_t)(n0 + row) * LL + f) * DD + c4 * 4);
        float4 sv = *(const float4*)(S + soff);
        Ss[row][c4 * 4 + 0] = tf32cvt(sv.x); Ss[row][c4 * 4 + 1] = tf32cvt(sv.y);
        Ss[row][c4 * 4 + 2] = tf32cvt(sv.z); Ss[row][c4 * 4 + 3] = tf32cvt(sv.w);
    }
    __syncthreads();

    float acc[4][4];
#pragma unroll
    for (int i = 0; i < 4; i++)
#pragma unroll
        for (int j = 0; j < 4; j++) acc[i][j] = 0.f;

#pragma unroll
    for (int ks = 0; ks < 8; ks++) {
        const int kc = ks * 8 + (lane & 3);
        unsigned a0 = As[mstrip + (lane >> 2)][kc];
        unsigned a1 = As[mstrip + (lane >> 2) + 8][kc];
        unsigned a2 = As[mstrip + (lane >> 2)][kc + 4];
        unsigned a3 = As[mstrip + (lane >> 2) + 8][kc + 4];
#pragma unroll
        for (int nt = 0; nt < 4; nt++) {
            const int nb = nh + nt * 8;
            unsigned b0 = Ss[nb + (lane >> 2)][kc];
            unsigned b1 = Ss[nb + (lane >> 2)][kc + 4];
            mma_tf32(acc[nt][0], acc[nt][1], acc[nt][2], acc[nt][3],
                     a0, a1, a2, a3, b0, b1);
        }
    }

    const int row0 = mstrip + (lane >> 2);   // bh index
#pragma unroll
    for (int nt = 0; nt < 4; nt++) {
        const int col = n0 + nh + nt * 8 + 2 * (lane & 3);
#pragma unroll
        for (int half = 0; half < 2; half++) {
            const int bh = row0 + half * 8;
            if (bh >= BH) continue;
            if (variant == 0) {
                const int b_idx = bh / HH;
                __nv_bfloat162 bv = __floats2bfloat162_rn(
                    acc[nt][2 * half + 0] + mask[b_idx * LL + col + 0],
                    acc[nt][2 * half + 1] + mask[b_idx * LL + col + 1]);
                *(__nv_bfloat162*)&g_biasq[((size_t)bh * LL + f) * LL + col] = bv;
            } else {
                __nv_bfloat162 bv = __floats2bfloat162_rn(
                    acc[nt][2 * half + 0] * 0.125f,
                    acc[nt][2 * half + 1] * 0.125f);
                *(__nv_bfloat162*)&g_biaskT[((size_t)bh * LL + f) * LL + col] = bv;
            }
        }
    }
}

// ============================================================================
// K3: fused flash attention.  All operands pre-converted to tf32 in gmem:
// mma fragment loads are pure LDS (no per-fragment cvt, no prep pass).
// cp.async double-buffered; P@V compensated (3 mmas).
// ============================================================================
#define RC      32
#define SPW     36
#define QSW     68

// smem layout (float units)
#define OFF_QS    0                       // 64*68 = 4352
#define OFF_KS0   4352                    // 32*68 = 2176
#define OFF_KS1   6528
#define OFF_VH0   8704
#define OFF_VH1   10880
#define OFF_VL0   13056
#define OFF_VL1   15232
#define OFF_SP    17408                   // 64*36 = 2304
#define OFF_PL    19712
#define OFF_BQ0   22016                   // 64*40 bf16 = 1280 floats
#define OFF_BQ1   23296
#define OFF_TS    24576                   // 64*34 bf16 = 1088 floats
#define OFF_MS    25664
#define OFF_SU    25728
#define OFF_SC    25792
#define SMEM_FLOATS 25856                 // 103424 B

__global__ __launch_bounds__(256) void fused_attn_kernel(float* __restrict__ out)
{
    extern __shared__ float sm[];
    float* Qs = sm + OFF_QS;
    float* Sp = sm + OFF_SP;
    float* Pl = sm + OFF_PL;
    float* m_state   = sm + OFF_MS;
    float* sum_state = sm + OFF_SU;
    float* scalef    = sm + OFF_SC;

    const int tid  = threadIdx.x;
    const int lane = tid & 31;
    const int warp = tid >> 5;
    const int bh   = blockIdx.y;
    const int l0   = blockIdx.x * 64;

    const int mstrip = (warp & 3) * 16;
    const int nh2    = (warp >> 2) * 16;   // qk N = 32
    const int nhpv   = (warp >> 2) * 32;   // pv N = 64
    const int arow   = mstrip + (lane >> 2);
    const int kcl    = lane & 3;

    // ---- prologue: Q tile (already tf32 bits) -> smem ----
#pragma unroll
    for (int i = 0; i < 4; i++) {
        const int idx = tid + i * 256;
        const int row = idx >> 4;
        const int c4  = idx & 15;
        *(float4*)&Qs[row * QSW + c4 * 4] =
            *(const float4*)(g_q + ((size_t)bh * LL + l0 + row) * DD + c4 * 4);
    }
    if (tid < 64) { m_state[tid] = -1e30f; sum_state[tid] = 0.f; }

    const int krow = tid >> 4, kseg = tid & 15;            // K/Vh/Vl
    const int brow = tid >> 2, bseg = tid & 3;             // Bq
    const int trow = tid >> 3, tseg = tid & 7;             // Ts LDG

    auto stage = [&](int rc, int db) {
        float* Ks = sm + (db ? OFF_KS1 : OFF_KS0);
        float* Vh = sm + (db ? OFF_VH1 : OFF_VH0);
        float* Vl = sm + (db ? OFF_VL1 : OFF_VL0);
        __nv_bfloat16* Bq = (__nv_bfloat16*)(sm + (db ? OFF_BQ1 : OFF_BQ0));
#pragma unroll
        for (int i = 0; i < 2; i++) {
            const int row = krow + i * 16;
            const size_t goff = ((size_t)bh * LL + rc + row) * DD + kseg * 4;
            cp16(&Ks[row * QSW + kseg * 4], g_k + goff);
            cp16(&Vh[row * QSW + kseg * 4], g_v + goff);
            cp16(&Vl[row * QSW + kseg * 4], g_vl + goff);
        }
        cp16(&Bq[brow * 40 + bseg * 8],
             g_biasq + ((size_t)bh * LL + l0 + brow) * LL + rc + bseg * 8);
        asm volatile("cp.async.commit_group;" ::: "memory");
    };
    auto ldg_ts = [&](int rc) -> uint4 {
        return *(const uint4*)(g_biaskT + ((size_t)bh * LL + rc + trow) * LL + l0 + tseg * 8);
    };

    float accpv[4][4];
#pragma unroll
    for (int i = 0; i < 4; i++)
#pragma unroll
        for (int j = 0; j < 4; j++) accpv[i][j] = 0.f;

    uint4 ts_reg = ldg_ts(0);
    stage(0, 0);

    for (int ci = 0; ci < LL / RC; ci++) {
        const int cur = ci & 1;
        float* Ks = sm + (cur ? OFF_KS1 : OFF_KS0);
        float* Vh = sm + (cur ? OFF_VH1 : OFF_VH0);
        float* Vl = sm + (cur ? OFF_VL1 : OFF_VL0);
        __nv_bfloat16* Bq = (__nv_bfloat16*)(sm + (cur ? OFF_BQ1 : OFF_BQ0));
        unsigned short* TsL = (unsigned short*)(sm + OFF_TS);

        // wait for chunk cur; barrier also closes reads of buffer cur^1
        asm volatile("cp.async.wait_group 0;" ::: "memory");
        __syncthreads();

        uint4 ts_next;
        if (ci + 1 < LL / RC) {
            ts_next = ldg_ts((ci + 1) * RC);
            stage((ci + 1) * RC, cur ^ 1);
        }

        // Ts transpose store: TsL[l][r], stride 34 halfwords
        {
            const unsigned short* h = (const unsigned short*)&ts_reg;
#pragma unroll
            for (int j = 0; j < 8; j++)
                TsL[(tseg * 8 + j) * 34 + trow] = h[j];
        }

        // ---- qk mma (pure LDS) ----
        float accqk[2][4];
#pragma unroll
        for (int i = 0; i < 2; i++)
#pragma unroll
            for (int j = 0; j < 4; j++) accqk[i][j] = 0.f;
#pragma unroll
        for (int ks = 0; ks < 8; ks++) {
            const int kc = ks * 8 + kcl;
            unsigned a0 = __float_as_uint(Qs[arow * QSW + kc]);
            unsigned a1 = __float_as_uint(Qs[(arow + 8) * QSW + kc]);
            unsigned a2 = __float_as_uint(Qs[arow * QSW + kc + 4]);
            unsigned a3 = __float_as_uint(Qs[(arow + 8) * QSW + kc + 4]);
#pragma unroll
            for (int nt = 0; nt < 2; nt++) {
                const int nb = nh2 + nt * 8 + (lane >> 2);
                unsigned b0 = __float_as_uint(Ks[nb * QSW + kc]);
                unsigned b1 = __float_as_uint(Ks[nb * QSW + kc + 4]);
                mma_tf32(accqk[nt][0], accqk[nt][1], accqk[nt][2], accqk[nt][3],
                         a0, a1, a2, a3, b0, b1);
            }
        }
#pragma unroll
        for (int nt = 0; nt < 2; nt++) {
            const int col = nh2 + nt * 8 + 2 * (lane & 3);
#pragma unroll
            for (int half = 0; half < 2; half++) {
                const int row = arow + half * 8;
                *(float2*)&Sp[row * SPW + col] =
                    make_float2(accqk[nt][2 * half + 0], accqk[nt][2 * half + 1]);
            }
        }
        __syncthreads();                    // Sp + TsL ready

        // ---- merged stats + P (thread owns l = tid>>2, r = (tid&3)*8..+7) ----
        {
            const int l  = tid >> 2;
            const int c0 = (tid & 3) * 8;
            const float mv_old = m_state[l];
            float s[8];
            {
                float4 sp0 = *(float4*)&Sp[l * SPW + c0];
                float4 sp1 = *(float4*)&Sp[l * SPW + c0 + 4];
                const __nv_bfloat162* bq2 = (const __nv_bfloat162*)&Bq[l * 40 + c0];
                const __nv_bfloat162* ts2 = (const __nv_bfloat162*)&TsL[l * 34 + c0];
                float2 b0 = __bfloat1622float2(bq2[0]);
                float2 b1 = __bfloat1622float2(bq2[1]);
                float2 b2 = __bfloat1622float2(bq2[2]);
                float2 b3 = __bfloat1622float2(bq2[3]);
                float2 t0 = __bfloat1622float2(ts2[0]);
                float2 t1 = __bfloat1622float2(ts2[1]);
                float2 t2 = __bfloat1622float2(ts2[2]);
                float2 t3 = __bfloat1622float2(ts2[3]);
                s[0] = sp0.x + b0.x + t0.x;  s[1] = sp0.y + b0.y + t0.y;
                s[2] = sp0.z + b1.x + t1.x;  s[3] = sp0.w + b1.y + t1.y;
                s[4] = sp1.x + b2.x + t2.x;  s[5] = sp1.y + b2.y + t2.y;
                s[6] = sp1.z + b3.x + t3.x;  s[7] = sp1.w + b3.y + t3.y;
            }
            float mc = s[0];
#pragma unroll
            for (int j = 1; j < 8; j++) mc = fmaxf(mc, s[j]);
            mc = fmaxf(mc, __shfl_xor_sync(0xffffffffu, mc, 1));
            mc = fmaxf(mc, __shfl_xor_sync(0xffffffffu, mc, 2));
            const float mnew = fmaxf(mv_old, mc);
            float e = 0.f;
            float pv[8], ph[8];
#pragma unroll
            for (int j = 0; j < 8; j++) {
                pv[j] = __expf(s[j] - mnew);
                e += pv[j];
                ph[j] = __uint_as_float(tf32cvt(pv[j]));
            }
            float4 p0, p1, q0, q1;
            p0.x = ph[0]; p0.y = ph[1]; p0.z = ph[2]; p0.w = ph[3];
            p1.x = ph[4]; p1.y = ph[5]; p1.z = ph[6]; p1.w = ph[7];
            q0.x = __uint_as_float(tf32cvt(pv[0] - ph[0]));
            q0.y = __uint_as_float(tf32cvt(pv[1] - ph[1]));
            q0.z = __uint_as_float(tf32cvt(pv[2] - ph[2]));
            q0.w = __uint_as_float(tf32cvt(pv[3] - ph[3]));
            q1.x = __uint_as_float(tf32cvt(pv[4] - ph[4]));
            q1.y = __uint_as_float(tf32cvt(pv[5] - ph[5]));
            q1.z = __uint_as_float(tf32cvt(pv[6] - ph[6]));
            q1.w = __uint_as_float(tf32cvt(pv[7] - ph[7]));
            *(float4*)&Sp[l * SPW + c0]     = p0;
            *(float4*)&Sp[l * SPW + c0 + 4] = p1;
            *(float4*)&Pl[l * SPW + c0]     = q0;
            *(float4*)&Pl[l * SPW + c0 + 4] = q1;
            e += __shfl_xor_sync(0xffffffffu, e, 1);
            e += __shfl_xor_sync(0xffffffffu, e, 2);
            if ((tid & 3) == 0) {
                const float sc = __expf(mv_old - mnew);
                scalef[l] = sc;
                sum_state[l] = sum_state[l] * sc + e;
                m_state[l] = mnew;
            }
        }
        __syncthreads();                    // P + scalef ready

        // ---- rescale + compensated P@V mma (pure LDS) ----
        {
            const float sc0 = scalef[arow];
            const float sc1 = scalef[arow + 8];
#pragma unroll
            for (int nt = 0; nt < 4; nt++) {
                accpv[nt][0] *= sc0; accpv[nt][1] *= sc0;
                accpv[nt][2] *= sc1; accpv[nt][3] *= sc1;
            }
        }
#pragma unroll
        for (int ks = 0; ks < 4; ks++) {
            const int kc = ks * 8 + kcl;
            unsigned ah0 = __float_as_uint(Sp[arow * SPW + kc]);
            unsigned ah1 = __float_as_uint(Sp[(arow + 8) * SPW + kc]);
            unsigned ah2 = __float_as_uint(Sp[arow * SPW + kc + 4]);
            unsigned ah3 = __float_as_uint(Sp[(arow + 8) * SPW + kc + 4]);
            unsigned al0 = __float_as_uint(Pl[arow * SPW + kc]);
            unsigned al1 = __float_as_uint(Pl[(arow + 8) * SPW + kc]);
            unsigned al2 = __float_as_uint(Pl[arow * SPW + kc + 4]);
            unsigned al3 = __float_as_uint(Pl[(arow + 8) * SPW + kc + 4]);
#pragma unroll
            for (int nt = 0; nt < 4; nt++) {
                const int nb = nhpv + nt * 8 + (lane >> 2);
                unsigned bh0 = __float_as_uint(Vh[(ks * 8 + kcl) * QSW + nb]);
                unsigned bh1 = __float_as_uint(Vh[(ks * 8 + kcl + 4) * QSW + nb]);
                unsigned bl0 = __float_as_uint(Vl[(ks * 8 + kcl) * QSW + nb]);
                unsigned bl1 = __float_as_uint(Vl[(ks * 8 + kcl + 4) * QSW + nb]);
                mma_tf32(accpv[nt][0], accpv[nt][1], accpv[nt][2], accpv[nt][3],
                         ah0, ah1, ah2, ah3, bh0, bh1);
                mma_tf32(accpv[nt][0], accpv[nt][1], accpv[nt][2], accpv[nt][3],
                         al0, al1, al2, al3, bh0, bh1);
                mma_tf32(accpv[nt][0], accpv[nt][1], accpv[nt][2], accpv[nt][3],
                         ah0, ah1, ah2, ah3, bl0, bl1);
            }
        }
        ts_reg = ts_next;
    }

    // ---- write out[b, l, h*64 + d] ----
    const int b_idx = bh / HH;
    const int h     = bh % HH;
#pragma unroll
    for (int half = 0; half < 2; half++) {
        const int row = arow + half * 8;
        const float inv = 1.f / sum_state[row];
        const int l = l0 + row;
#pragma unroll
        for (int nt = 0; nt < 4; nt++) {
            const int col = nhpv + nt * 8 + 2 * (lane & 3);
            float2 r;
            r.x = accpv[nt][2 * half + 0] * inv;
            r.y = accpv[nt][2 * half + 1] * inv;
            *(float2*)&out[((size_t)(b_idx * LL + l)) * HIDD + h * DD + col] = r;
        }
    }
}

// ============================================================================
// launch
// ============================================================================
extern "C" void kernel_launch(void* const* d_in, const int* in_sizes, int n_in,
                              void* d_out, int out_size)
{
    (void)in_sizes; (void)n_in; (void)out_size;
    const float* hidden = (const float*)d_in[0];
    const float* mask   = (const float*)d_in[1];
    const float* S      = (const float*)d_in[2];
    const float* Wq     = (const float*)d_in[3];
    const float* bq     = (const float*)d_in[4];
    const float* Wk     = (const float*)d_in[5];
    const float* bk     = (const float*)d_in[6];
    const float* Wv     = (const float*)d_in[7];
    const float* bv     = (const float*)d_in[8];
    float* out = (float*)d_out;

    static int smem_set = 0;
    if (!smem_set) {
        cudaFuncSetAttribute(fused_attn_kernel,
                             cudaFuncAttributeMaxDynamicSharedMemorySize,
                             SMEM_FLOATS * (int)sizeof(float));
        smem_set = 1;
    }

    dim3 g1(64, 12, 3);
    qkv_mma_kernel<<<g1, 256>>>(hidden, Wq, bq, Wk, bk, Wv, bv);

    dim3 g2(16, 1024);
    bias_mma_kernel<<<g2, 256>>>(S, mask, 0);   // q-side -> g_biasq (bf16, +mask)
    bias_mma_kernel<<<g2, 256>>>(S, mask, 1);   // k-side -> g_biaskT (bf16)

    dim3 g3(16, 48);
    fused_attn_kernel<<<g3, 256, SMEM_FLOATS * sizeof(float)>>>(out);
}

// round 10
// speedup vs baseline: 1.2801x; 1.1701x over previous
#include <cuda_runtime.h>
#include <cuda_bf16.h>
#include <math.h>

#define BB   4
#define LL   1024
#define HIDD 768
#define HH   12
#define DD   64
#define BH   (BB*HH)

// ---- scratch (device globals; no allocation allowed) ----
__device__ float g_q[BH * LL * DD];                        // [bh, l, d] tf32 bits (pre-scaled 0.125)
__device__ float g_k[BH * LL * DD];                        // [bh, l, d] tf32 bits
__device__ float g_v[BH * LL * DD];                        // [bh, l, d] tf32 bits
__device__ __nv_bfloat16 g_biasq[(size_t)BH * LL * LL];    // [bh, l, r] = qS/8 + mask
__device__ __nv_bfloat16 g_biaskT[(size_t)BH * LL * LL];   // [bh, r, l] = kS/8

// ---------------- helpers ----------------
__device__ __forceinline__ unsigned tf32cvt(float x) {
    unsigned u;
    asm("cvt.rna.tf32.f32 %0, %1;" : "=r"(u) : "f"(x));
    return u;
}
__device__ __forceinline__ void mma_tf32(float& c0, float& c1, float& c2, float& c3,
                                         unsigned a0, unsigned a1, unsigned a2, unsigned a3,
                                         unsigned b0, unsigned b1) {
    asm("mma.sync.aligned.m16n8k8.row.col.f32.tf32.tf32.f32 "
        "{%0,%1,%2,%3},{%4,%5,%6,%7},{%8,%9},{%0,%1,%2,%3};"
        : "+f"(c0), "+f"(c1), "+f"(c2), "+f"(c3)
        : "r"(a0), "r"(a1), "r"(a2), "r"(a3), "r"(b0), "r"(b1));
}
__device__ __forceinline__ void cp16(const void* smem_dst, const void* gsrc) {
    unsigned sa = (unsigned)__cvta_generic_to_shared(smem_dst);
    asm volatile("cp.async.cg.shared.global [%0], [%1], 16;" :: "r"(sa), "l"(gsrc));
}
__device__ __forceinline__ float2 bf2(unsigned u) {
    __nv_bfloat162 h = *reinterpret_cast<__nv_bfloat162*>(&u);
    return __bfloat1622float2(h);
}

// ============================================================================
// K1: QKV projection, tf32 mma, register double-buffered staging.
// Outputs stored as tf32-bit floats (consumers do zero conversions).
// ============================================================================
__global__ __launch_bounds__(256) void qkv_mma_kernel(
    const float* __restrict__ X,
    const float* __restrict__ W,
    const float* __restrict__ bias,
    int which)
{
    __shared__ unsigned Xs[64][68];
    __shared__ unsigned Ws[64][68];

    const int tid  = threadIdx.x;
    const int warp = tid >> 5;
    const int lane = tid & 31;
    const int m0 = blockIdx.x * 64;
    const int n0 = blockIdx.y * 64;
    const int mstrip = (warp & 3) * 16;
    const int nh     = (warp >> 2) * 32;

    float acc[4][4];
#pragma unroll
    for (int i = 0; i < 4; i++)
#pragma unroll
        for (int j = 0; j < 4; j++) acc[i][j] = 0.f;

    float4 xr[4], wr[4];
#pragma unroll
    for (int i = 0; i < 4; i++) {
        const int idx = tid + i * 256;
        const int row = idx >> 4;
        const int c4  = idx & 15;
        xr[i] = *(const float4*)(X + (size_t)(m0 + row) * HIDD + c4 * 4);
        wr[i] = *(const float4*)(W + (size_t)(n0 + row) * HIDD + c4 * 4);
    }

    for (int k0 = 0; k0 < HIDD; k0 += 64) {
        __syncthreads();
#pragma unroll
        for (int i = 0; i < 4; i++) {
            const int idx = tid + i * 256;
            const int row = idx >> 4;
            const int c4  = idx & 15;
            Xs[row][c4 * 4 + 0] = tf32cvt(xr[i].x); Xs[row][c4 * 4 + 1] = tf32cvt(xr[i].y);
            Xs[row][c4 * 4 + 2] = tf32cvt(xr[i].z); Xs[row][c4 * 4 + 3] = tf32cvt(xr[i].w);
            Ws[row][c4 * 4 + 0] = tf32cvt(wr[i].x); Ws[row][c4 * 4 + 1] = tf32cvt(wr[i].y);
            Ws[row][c4 * 4 + 2] = tf32cvt(wr[i].z); Ws[row][c4 * 4 + 3] = tf32cvt(wr[i].w);
        }
        __syncthreads();
        if (k0 + 64 < HIDD) {
#pragma unroll
            for (int i = 0; i < 4; i++) {
                const int idx = tid + i * 256;
                const int row = idx >> 4;
                const int c4  = idx & 15;
                xr[i] = *(const float4*)(X + (size_t)(m0 + row) * HIDD + k0 + 64 + c4 * 4);
                wr[i] = *(const float4*)(W + (size_t)(n0 + row) * HIDD + k0 + 64 + c4 * 4);
            }
        }
#pragma unroll
        for (int ks = 0; ks < 8; ks++) {
            const int kc = ks * 8 + (lane & 3);
            unsigned a0 = Xs[mstrip + (lane >> 2)][kc];
            unsigned a1 = Xs[mstrip + (lane >> 2) + 8][kc];
            unsigned a2 = Xs[mstrip + (lane >> 2)][kc + 4];
            unsigned a3 = Xs[mstrip + (lane >> 2) + 8][kc + 4];
#pragma unroll
            for (int nt = 0; nt < 4; nt++) {
                const int nb = nh + nt * 8;
                unsigned b0 = Ws[nb + (lane >> 2)][kc];
                unsigned b1 = Ws[nb + (lane >> 2)][kc + 4];
                mma_tf32(acc[nt][0], acc[nt][1], acc[nt][2], acc[nt][3],
                         a0, a1, a2, a3, b0, b1);
            }
        }
    }

    float* out = (which == 0) ? g_q : (which == 1) ? g_k : g_v;
    const float scale = (which == 0) ? 0.125f : 1.0f;
    const int row0 = m0 + mstrip + (lane >> 2);
#pragma unroll
    for (int nt = 0; nt < 4; nt++) {
        const int col = n0 + nh + nt * 8 + 2 * (lane & 3);
        const int h = col >> 6;
        const int d = col & 63;
#pragma unroll
        for (int half = 0; half < 2; half++) {
            const int row = row0 + half * 8;
            const int b_idx = row >> 10;
            const int l     = row & (LL - 1);
            float2 r;
            r.x = __uint_as_float(tf32cvt((acc[nt][2 * half + 0] + bias[col + 0]) * scale));
            r.y = __uint_as_float(tf32cvt((acc[nt][2 * half + 1] + bias[col + 1]) * scale));
            *(float2*)&out[(((size_t)b_idx * HH + h) * LL + l) * DD + d] = r;
        }
    }
}

// ============================================================================
// K2: structure-bias GEMMs (bf16 output).  g_q/g_k already tf32 bits.
//  variant 0 (f=l): g_biasq[bh, f, n]  = q.S[f,n,:] + mask[b,n]
//  variant 1 (f=r): g_biaskT[bh, f, n] = 0.125 * k.S[n,f,:]
// ============================================================================
__global__ __launch_bounds__(256) void bias_mma_kernel(
    const float* __restrict__ S, const float* __restrict__ mask, int variant)
{
    __shared__ unsigned As[64][68];
    __shared__ unsigned Ss[64][68];

    const int tid  = threadIdx.x;
    const int warp = tid >> 5;
    const int lane = tid & 31;
    const int n0 = blockIdx.x * 64;
    const int f  = blockIdx.y;
    const int mstrip = (warp & 3) * 16;
    const int nh     = (warp >> 2) * 32;

    const float* Aop = (variant == 0) ? g_q : g_k;

#pragma unroll
    for (int i = 0; i < 4; i++) {
        const int idx = tid + i * 256;
        const int row = idx >> 4;
        const int c4  = idx & 15;
        if (row < BH) {
            float4 av = *(const float4*)(Aop + ((size_t)row * LL + f) * DD + c4 * 4);
            As[row][c4 * 4 + 0] = __float_as_uint(av.x);
            As[row][c4 * 4 + 1] = __float_as_uint(av.y);
            As[row][c4 * 4 + 2] = __float_as_uint(av.z);
            As[row][c4 * 4 + 3] = __float_as_uint(av.w);
        } else {
            As[row][c4 * 4 + 0] = 0u; As[row][c4 * 4 + 1] = 0u;
            As[row][c4 * 4 + 2] = 0u; As[row][c4 * 4 + 3] = 0u;
        }
        size_t soff = (variant == 0)
            ? (((size_t)f * LL + n0 + row) * DD + c4 * 4)
            : (((size_t)(n0 + row) * LL + f) * DD + c4 * 4);
        float4 sv = *(const float4*)(S + soff);
        Ss[row][c4 * 4 + 0] = tf32cvt(sv.x); Ss[row][c4 * 4 + 1] = tf32cvt(sv.y);
        Ss[row][c4 * 4 + 2] = tf32cvt(sv.z); Ss[row][c4 * 4 + 3] = tf32cvt(sv.w);
    }
    __syncthreads();

    float acc[4][4];
#pragma unroll
    for (int i = 0; i < 4; i++)
#pragma unroll
        for (int j = 0; j < 4; j++) acc[i][j] = 0.f;

#pragma unroll
    for (int ks = 0; ks < 8; ks++) {
        const int kc = ks * 8 + (lane & 3);
        unsigned a0 = As[mstrip + (lane >> 2)][kc];
        unsigned a1 = As[mstrip + (lane >> 2) + 8][kc];
        unsigned a2 = As[mstrip + (lane >> 2)][kc + 4];
        unsigned a3 = As[mstrip + (lane >> 2) + 8][kc + 4];
#pragma unroll
        for (int nt = 0; nt < 4; nt++) {
            const int nb = nh + nt * 8;
            unsigned b0 = Ss[nb + (lane >> 2)][kc];
            unsigned b1 = Ss[nb + (lane >> 2)][kc + 4];
            mma_tf32(acc[nt][0], acc[nt][1], acc[nt][2], acc[nt][3],
                     a0, a1, a2, a3, b0, b1);
        }
    }

    const int row0 = mstrip + (lane >> 2);   // bh index
#pragma unroll
    for (int nt = 0; nt < 4; nt++) {
        const int col = n0 + nh + nt * 8 + 2 * (lane & 3);
#pragma unroll
        for (int half = 0; half < 2; half++) {
            const int bh = row0 + half * 8;
            if (bh >= BH) continue;
            if (variant == 0) {
                const int b_idx = bh / HH;
                __nv_bfloat162 bv = __floats2bfloat162_rn(
                    acc[nt][2 * half + 0] + mask[b_idx * LL + col + 0],
                    acc[nt][2 * half + 1] + mask[b_idx * LL + col + 1]);
                *(__nv_bfloat162*)&g_biasq[((size_t)bh * LL + f) * LL + col] = bv;
            } else {
                __nv_bfloat162 bv = __floats2bfloat162_rn(
                    acc[nt][2 * half + 0] * 0.125f,
                    acc[nt][2 * half + 1] * 0.125f);
                *(__nv_bfloat162*)&g_biaskT[((size_t)bh * LL + f) * LL + col] = bv;
            }
        }
    }
}

// ============================================================================
// K3: fused flash attention.  75.8 KB smem -> 3 CTAs/SM.
// K/V via cp.async double buffer; biasq + biaskT via register LDG prefetch.
// P@V with P-compensation only (Phi*V + Plo*V).
// ============================================================================
#define RC      32
#define SPW     36
#define QSW     68

// smem layout (float units)
#define OFF_QS    0                       // 64*68 = 4352
#define OFF_KS0   4352                    // 32*68 = 2176
#define OFF_KS1   6528
#define OFF_VH0   8704
#define OFF_VH1   10880
#define OFF_SP    13056                   // 64*36 = 2304
#define OFF_PL    15360                   // 64*36 = 2304
#define OFF_TS    17664                   // 64*34 bf16 = 1088 floats
#define OFF_MS    18752
#define OFF_SU    18816
#define OFF_SC    18880
#define SMEM_FLOATS 18944                 // 75776 B

__global__ __launch_bounds__(256) void fused_attn_kernel(float* __restrict__ out)
{
    extern __shared__ float sm[];
    float* Qs = sm + OFF_QS;
    float* Sp = sm + OFF_SP;
    float* Pl = sm + OFF_PL;
    float* m_state   = sm + OFF_MS;
    float* sum_state = sm + OFF_SU;
    float* scalef    = sm + OFF_SC;

    const int tid  = threadIdx.x;
    const int lane = tid & 31;
    const int warp = tid >> 5;
    const int bh   = blockIdx.y;
    const int l0   = blockIdx.x * 64;

    const int mstrip = (warp & 3) * 16;
    const int nh2    = (warp >> 2) * 16;   // qk N = 32
    const int nhpv   = (warp >> 2) * 32;   // pv N = 64
    const int arow   = mstrip + (lane >> 2);
    const int kcl    = lane & 3;

    // ---- prologue: Q tile (tf32 bits) -> smem ----
#pragma unroll
    for (int i = 0; i < 4; i++) {
        const int idx = tid + i * 256;
        const int row = idx >> 4;
        const int c4  = idx & 15;
        *(float4*)&Qs[row * QSW + c4 * 4] =
            *(const float4*)(g_q + ((size_t)bh * LL + l0 + row) * DD + c4 * 4);
    }
    if (tid < 64) { m_state[tid] = -1e30f; sum_state[tid] = 0.f; }

    const int krow = tid >> 4, kseg = tid & 15;            // K/V staging
    const int trow = tid >> 3, tseg = tid & 7;             // Ts LDG
    const int bql  = tid >> 2, bqc  = (tid & 3) * 8;       // Bq LDG (owner layout)

    auto stage = [&](int rc, int db) {
        float* Ks = sm + (db ? OFF_KS1 : OFF_KS0);
        float* Vh = sm + (db ? OFF_VH1 : OFF_VH0);
#pragma unroll
        for (int i = 0; i < 2; i++) {
            const int row = krow + i * 16;
            const size_t goff = ((size_t)bh * LL + rc + row) * DD + kseg * 4;
            cp16(&Ks[row * QSW + kseg * 4], g_k + goff);
            cp16(&Vh[row * QSW + kseg * 4], g_v + goff);
        }
        asm volatile("cp.async.commit_group;" ::: "memory");
    };
    auto ldg_ts = [&](int rc) -> uint4 {
        return *(const uint4*)(g_biaskT + ((size_t)bh * LL + rc + trow) * LL + l0 + tseg * 8);
    };
    auto ldg_bq = [&](int rc) -> uint4 {
        return *(const uint4*)(g_biasq + ((size_t)bh * LL + l0 + bql) * LL + rc + bqc);
    };

    float accpv[4][4];
#pragma unroll
    for (int i = 0; i < 4; i++)
#pragma unroll
        for (int j = 0; j < 4; j++) accpv[i][j] = 0.f;

    uint4 ts_reg = ldg_ts(0);
    uint4 bq_reg = ldg_bq(0);
    stage(0, 0);

    for (int ci = 0; ci < LL / RC; ci++) {
        const int cur = ci & 1;
        float* Ks = sm + (cur ? OFF_KS1 : OFF_KS0);
        float* Vh = sm + (cur ? OFF_VH1 : OFF_VH0);
        unsigned short* TsL = (unsigned short*)(sm + OFF_TS);

        // wait for chunk cur; barrier also closes reads of buffer cur^1 + TsL
        asm volatile("cp.async.wait_group 0;" ::: "memory");
        __syncthreads();

        uint4 ts_next, bq_next;
        if (ci + 1 < LL / RC) {
            ts_next = ldg_ts((ci + 1) * RC);
            bq_next = ldg_bq((ci + 1) * RC);
            stage((ci + 1) * RC, cur ^ 1);
        }

        // Ts transpose store: TsL[l][r], stride 34 halfwords
        {
            const unsigned short* h = (const unsigned short*)&ts_reg;
#pragma unroll
            for (int j = 0; j < 8; j++)
                TsL[(tseg * 8 + j) * 34 + trow] = h[j];
        }

        // ---- qk mma (pure LDS) ----
        float accqk[2][4];
#pragma unroll
        for (int i = 0; i < 2; i++)
#pragma unroll
            for (int j = 0; j < 4; j++) accqk[i][j] = 0.f;
#pragma unroll
        for (int ks = 0; ks < 8; ks++) {
            const int kc = ks * 8 + kcl;
            unsigned a0 = __float_as_uint(Qs[arow * QSW + kc]);
            unsigned a1 = __float_as_uint(Qs[(arow + 8) * QSW + kc]);
            unsigned a2 = __float_as_uint(Qs[arow * QSW + kc + 4]);
            unsigned a3 = __float_as_uint(Qs[(arow + 8) * QSW + kc + 4]);
#pragma unroll
            for (int nt = 0; nt < 2; nt++) {
                const int nb = nh2 + nt * 8 + (lane >> 2);
                unsigned b0 = __float_as_uint(Ks[nb * QSW + kc]);
                unsigned b1 = __float_as_uint(Ks[nb * QSW + kc + 4]);
                mma_tf32(accqk[nt][0], accqk[nt][1], accqk[nt][2], accqk[nt][3],
                         a0, a1, a2, a3, b0, b1);
            }
        }
#pragma unroll
        for (int nt = 0; nt < 2; nt++) {
            const int col = nh2 + nt * 8 + 2 * (lane & 3);
#pragma unroll
            for (int half = 0; half < 2; half++) {
                const int row = arow + half * 8;
                *(float2*)&Sp[row * SPW + col] =
                    make_float2(accqk[nt][2 * half + 0], accqk[nt][2 * half + 1]);
            }
        }
        __syncthreads();                    // Sp + TsL ready

        // ---- merged stats + P (thread owns l = tid>>2, r = (tid&3)*8..+7) ----
        {
            const int l  = bql;
            const int c0 = bqc;
            const float mv_old = m_state[l];
            float s[8];
            {
                float4 sp0 = *(float4*)&Sp[l * SPW + c0];
                float4 sp1 = *(float4*)&Sp[l * SPW + c0 + 4];
                const __nv_bfloat162* ts2 = (const __nv_bfloat162*)&TsL[l * 34 + c0];
                float2 b0 = bf2(bq_reg.x);
                float2 b1 = bf2(bq_reg.y);
                float2 b2 = bf2(bq_reg.z);
                float2 b3 = bf2(bq_reg.w);
                float2 t0 = __bfloat1622float2(ts2[0]);
                float2 t1 = __bfloat1622float2(ts2[1]);
                float2 t2 = __bfloat1622float2(ts2[2]);
                float2 t3 = __bfloat1622float2(ts2[3]);
                s[0] = sp0.x + b0.x + t0.x;  s[1] = sp0.y + b0.y + t0.y;
                s[2] = sp0.z + b1.x + t1.x;  s[3] = sp0.w + b1.y + t1.y;
                s[4] = sp1.x + b2.x + t2.x;  s[5] = sp1.y + b2.y + t2.y;
                s[6] = sp1.z + b3.x + t3.x;  s[7] = sp1.w + b3.y + t3.y;
            }
            float mc = s[0];
#pragma unroll
            for (int j = 1; j < 8; j++) mc = fmaxf(mc, s[j]);
            mc = fmaxf(mc, __shfl_xor_sync(0xffffffffu, mc, 1));
            mc = fmaxf(mc, __shfl_xor_sync(0xffffffffu, mc, 2));
            const float mnew = fmaxf(mv_old, mc);
            float e = 0.f;
            float pv[8], ph[8];
#pragma unroll
            for (int j = 0; j < 8; j++) {
                pv[j] = __expf(s[j] - mnew);
                e += pv[j];
                ph[j] = __uint_as_float(tf32cvt(pv[j]));
            }
            float4 p0, p1, q0, q1;
            p0.x = ph[0]; p0.y = ph[1]; p0.z = ph[2]; p0.w = ph[3];
            p1.x = ph[4]; p1.y = ph[5]; p1.z = ph[6]; p1.w = ph[7];
            q0.x = __uint_as_float(tf32cvt(pv[0] - ph[0]));
            q0.y = __uint_as_float(tf32cvt(pv[1] - ph[1]));
            q0.z = __uint_as_float(tf32cvt(pv[2] - ph[2]));
            q0.w = __uint_as_float(tf32cvt(pv[3] - ph[3]));
            q1.x = __uint_as_float(tf32cvt(pv[4] - ph[4]));
            q1.y = __uint_as_float(tf32cvt(pv[5] - ph[5]));
            q1.z = __uint_as_float(tf32cvt(pv[6] - ph[6]));
            q1.w = __uint_as_float(tf32cvt(pv[7] - ph[7]));
            *(float4*)&Sp[l * SPW + c0]     = p0;
            *(float4*)&Sp[l * SPW + c0 + 4] = p1;
            *(float4*)&Pl[l * SPW + c0]     = q0;
            *(float4*)&Pl[l * SPW + c0 + 4] = q1;
            e += __shfl_xor_sync(0xffffffffu, e, 1);
            e += __shfl_xor_sync(0xffffffffu, e, 2);
            if ((tid & 3) == 0) {
                const float sc = __expf(mv_old - mnew);
                scalef[l] = sc;
                sum_state[l] = sum_state[l] * sc + e;
                m_state[l] = mnew;
            }
        }
        __syncthreads();                    // P + scalef ready

        // ---- rescale + P-compensated P@V mma ----
        {
            const float sc0 = scalef[arow];
            const float sc1 = scalef[arow + 8];
#pragma unroll
            for (int nt = 0; nt < 4; nt++) {
                accpv[nt][0] *= sc0; accpv[nt][1] *= sc0;
                accpv[nt][2] *= sc1; accpv[nt][3] *= sc1;
            }
        }
#pragma unroll
        for (int ks = 0; ks < 4; ks++) {
            const int kc = ks * 8 + kcl;
            unsigned ah0 = __float_as_uint(Sp[arow * SPW + kc]);
            unsigned ah1 = __float_as_uint(Sp[(arow + 8) * SPW + kc]);
            unsigned ah2 = __float_as_uint(Sp[arow * SPW + kc + 4]);
            unsigned ah3 = __float_as_uint(Sp[(arow + 8) * SPW + kc + 4]);
            unsigned al0 = __float_as_uint(Pl[arow * SPW + kc]);
            unsigned al1 = __float_as_uint(Pl[(arow + 8) * SPW + kc]);
            unsigned al2 = __float_as_uint(Pl[arow * SPW + kc + 4]);
            unsigned al3 = __float_as_uint(Pl[(arow + 8) * SPW + kc + 4]);
#pragma unroll
            for (int nt = 0; nt < 4; nt++) {
                const int nb = nhpv + nt * 8 + (lane >> 2);
                unsigned bh0 = __float_as_uint(Vh[(ks * 8 + kcl) * QSW + nb]);
                unsigned bh1 = __float_as_uint(Vh[(ks * 8 + kcl + 4) * QSW + nb]);
                mma_tf32(accpv[nt][0], accpv[nt][1], accpv[nt][2], accpv[nt][3],
                         ah0, ah1, ah2, ah3, bh0, bh1);
                mma_tf32(accpv[nt][0], accpv[nt][1], accpv[nt][2], accpv[nt][3],
                         al0, al1, al2, al3, bh0, bh1);
            }
        }
        ts_reg = ts_next;
        bq_reg = bq_next;
    }

    // ---- write out[b, l, h*64 + d] ----
    const int b_idx = bh / HH;
    const int h     = bh % HH;
#pragma unroll
    for (int half = 0; half < 2; half++) {
        const int row = arow + half * 8;
        const float inv = 1.f / sum_state[row];
        const int l = l0 + row;
#pragma unroll
        for (int nt = 0; nt < 4; nt++) {
            const int col = nhpv + nt * 8 + 2 * (lane & 3);
            float2 r;
            r.x = accpv[nt][2 * half + 0] * inv;
            r.y = accpv[nt][2 * half + 1] * inv;
            *(float2*)&out[((size_t)(b_idx * LL + l)) * HIDD + h * DD + col] = r;
        }
    }
}

// ============================================================================
// launch — fork/join streams: (q->bias0) || (k->bias1) || v, then fused.
// ============================================================================
extern "C" void kernel_launch(void* const* d_in, const int* in_sizes, int n_in,
                              void* d_out, int out_size)
{
    (void)in_sizes; (void)n_in; (void)out_size;
    const float* hidden = (const float*)d_in[0];
    const float* mask   = (const float*)d_in[1];
    const float* S      = (const float*)d_in[2];
    const float* Wq     = (const float*)d_in[3];
    const float* bq     = (const float*)d_in[4];
    const float* Wk     = (const float*)d_in[5];
    const float* bk     = (const float*)d_in[6];
    const float* Wv     = (const float*)d_in[7];
    const float* bv     = (const float*)d_in[8];
    float* out = (float*)d_out;

    static cudaStream_t s1 = 0, s2 = 0;
    static cudaEvent_t eR = 0, e1 = 0, e2 = 0;
    static int init_done = 0;
    if (!init_done) {
        cudaFuncSetAttribute(fused_attn_kernel,
                             cudaFuncAttributeMaxDynamicSharedMemorySize,
                             SMEM_FLOATS * (int)sizeof(float));
        cudaStreamCreateWithFlags(&s1, cudaStreamNonBlocking);
        cudaStreamCreateWithFlags(&s2, cudaStreamNonBlocking);
        cudaEventCreateWithFlags(&eR, cudaEventDisableTiming);
        cudaEventCreateWithFlags(&e1, cudaEventDisableTiming);
        cudaEventCreateWithFlags(&e2, cudaEventDisableTiming);
        init_done = 1;
    }

    dim3 g1(64, 12);
    dim3 g2(16, 1024);

    cudaEventRecord(eR, 0);
    cudaStreamWaitEvent(s1, eR, 0);
    cudaStreamWaitEvent(s2, eR, 0);

    // chain A (stream 0): q proj -> q-side bias
    qkv_mma_kernel<<<g1, 256, 0, 0>>>(hidden, Wq, bq, 0);
    bias_mma_kernel<<<g2, 256, 0, 0>>>(S, mask, 0);

    // chain B (s1): k proj -> k-side bias
    qkv_mma_kernel<<<g1, 256, 0, s1>>>(hidden, Wk, bk, 1);
    bias_mma_kernel<<<g2, 256, 0, s1>>>(S, mask, 1);

    // chain C (s2): v proj
    qkv_mma_kernel<<<g1, 256, 0, s2>>>(hidden, Wv, bv, 2);

    cudaEventRecord(e1, s1);
    cudaEventRecord(e2, s2);
    cudaStreamWaitEvent(0, e1, 0);
    cudaStreamWaitEvent(0, e2, 0);

    dim3 g3(16, 48);
    fused_attn_kernel<<<g3, 256, SMEM_FLOATS * sizeof(float)>>>(out);
}

// round 11
// speedup vs baseline: 1.4029x; 1.0959x over previous
#include <cuda_runtime.h>
#include <cuda_bf16.h>
#include <math.h>

#define BB   4
#define LL   1024
#define HIDD 768
#define HH   12
#define DD   64
#define BH   (BB*HH)

// ---- scratch (device globals; no allocation allowed) ----
__device__ float g_q[BH * LL * DD];                        // [bh, l, d] tf32 bits (pre-scaled 0.125)
__device__ float g_k[BH * LL * DD];                        // [bh, l, d] tf32 bits
__device__ float g_v[BH * LL * DD];                        // [bh, l, d] tf32 bits
__device__ __nv_bfloat16 g_biasq[(size_t)BH * LL * LL];    // [bh, l, r] = qS/8 + mask
__device__ __nv_bfloat16 g_biaskT[(size_t)BH * LL * LL];   // [bh, r, l] = kS/8

// ---------------- helpers ----------------
__device__ __forceinline__ unsigned tf32cvt(float x) {
    unsigned u;
    asm("cvt.rna.tf32.f32 %0, %1;" : "=r"(u) : "f"(x));
    return u;
}
__device__ __forceinline__ void mma_tf32(float& c0, float& c1, float& c2, float& c3,
                                         unsigned a0, unsigned a1, unsigned a2, unsigned a3,
                                         unsigned b0, unsigned b1) {
    asm("mma.sync.aligned.m16n8k8.row.col.f32.tf32.tf32.f32 "
        "{%0,%1,%2,%3},{%4,%5,%6,%7},{%8,%9},{%0,%1,%2,%3};"
        : "+f"(c0), "+f"(c1), "+f"(c2), "+f"(c3)
        : "r"(a0), "r"(a1), "r"(a2), "r"(a3), "r"(b0), "r"(b1));
}
__device__ __forceinline__ void cp16(const void* smem_dst, const void* gsrc) {
    unsigned sa = (unsigned)__cvta_generic_to_shared(smem_dst);
    asm volatile("cp.async.cg.shared.global [%0], [%1], 16;" :: "r"(sa), "l"(gsrc));
}
__device__ __forceinline__ float2 bf2(unsigned u) {
    __nv_bfloat162 h = *reinterpret_cast<__nv_bfloat162*>(&u);
    return __bfloat1622float2(h);
}

// ============================================================================
// K1: QKV projection, tf32 mma, register double-buffered staging.
// Outputs stored as tf32-bit floats (consumers do zero conversions).
// ============================================================================
__global__ __launch_bounds__(256) void qkv_mma_kernel(
    const float* __restrict__ X,
    const float* __restrict__ W,
    const float* __restrict__ bias,
    int which)
{
    __shared__ unsigned Xs[64][68];
    __shared__ unsigned Ws[64][68];

    const int tid  = threadIdx.x;
    const int warp = tid >> 5;
    const int lane = tid & 31;
    const int m0 = blockIdx.x * 64;
    const int n0 = blockIdx.y * 64;
    const int mstrip = (warp & 3) * 16;
    const int nh     = (warp >> 2) * 32;

    float acc[4][4];
#pragma unroll
    for (int i = 0; i < 4; i++)
#pragma unroll
        for (int j = 0; j < 4; j++) acc[i][j] = 0.f;

    float4 xr[4], wr[4];
#pragma unroll
    for (int i = 0; i < 4; i++) {
        const int idx = tid + i * 256;
        const int row = idx >> 4;
        const int c4  = idx & 15;
        xr[i] = *(const float4*)(X + (size_t)(m0 + row) * HIDD + c4 * 4);
        wr[i] = *(const float4*)(W + (size_t)(n0 + row) * HIDD + c4 * 4);
    }

    for (int k0 = 0; k0 < HIDD; k0 += 64) {
        __syncthreads();
#pragma unroll
        for (int i = 0; i < 4; i++) {
            const int idx = tid + i * 256;
            const int row = idx >> 4;
            const int c4  = idx & 15;
            Xs[row][c4 * 4 + 0] = tf32cvt(xr[i].x); Xs[row][c4 * 4 + 1] = tf32cvt(xr[i].y);
            Xs[row][c4 * 4 + 2] = tf32cvt(xr[i].z); Xs[row][c4 * 4 + 3] = tf32cvt(xr[i].w);
            Ws[row][c4 * 4 + 0] = tf32cvt(wr[i].x); Ws[row][c4 * 4 + 1] = tf32cvt(wr[i].y);
            Ws[row][c4 * 4 + 2] = tf32cvt(wr[i].z); Ws[row][c4 * 4 + 3] = tf32cvt(wr[i].w);
        }
        __syncthreads();
        if (k0 + 64 < HIDD) {
#pragma unroll
            for (int i = 0; i < 4; i++) {
                const int idx = tid + i * 256;
                const int row = idx >> 4;
                const int c4  = idx & 15;
                xr[i] = *(const float4*)(X + (size_t)(m0 + row) * HIDD + k0 + 64 + c4 * 4);
                wr[i] = *(const float4*)(W + (size_t)(n0 + row) * HIDD + k0 + 64 + c4 * 4);
            }
        }
#pragma unroll
        for (int ks = 0; ks < 8; ks++) {
            const int kc = ks * 8 + (lane & 3);
            unsigned a0 = Xs[mstrip + (lane >> 2)][kc];
            unsigned a1 = Xs[mstrip + (lane >> 2) + 8][kc];
            unsigned a2 = Xs[mstrip + (lane >> 2)][kc + 4];
            unsigned a3 = Xs[mstrip + (lane >> 2) + 8][kc + 4];
#pragma unroll
            for (int nt = 0; nt < 4; nt++) {
                const int nb = nh + nt * 8;
                unsigned b0 = Ws[nb + (lane >> 2)][kc];
                unsigned b1 = Ws[nb + (lane >> 2)][kc + 4];
                mma_tf32(acc[nt][0], acc[nt][1], acc[nt][2], acc[nt][3],
                         a0, a1, a2, a3, b0, b1);
            }
        }
    }

    float* out = (which == 0) ? g_q : (which == 1) ? g_k : g_v;
    const float scale = (which == 0) ? 0.125f : 1.0f;
    const int row0 = m0 + mstrip + (lane >> 2);
#pragma unroll
    for (int nt = 0; nt < 4; nt++) {
        const int col = n0 + nh + nt * 8 + 2 * (lane & 3);
        const int h = col >> 6;
        const int d = col & 63;
#pragma unroll
        for (int half = 0; half < 2; half++) {
            const int row = row0 + half * 8;
            const int b_idx = row >> 10;
            const int l     = row & (LL - 1);
            float2 r;
            r.x = __uint_as_float(tf32cvt((acc[nt][2 * half + 0] + bias[col + 0]) * scale));
            r.y = __uint_as_float(tf32cvt((acc[nt][2 * half + 1] + bias[col + 1]) * scale));
            *(float2*)&out[(((size_t)b_idx * HH + h) * LL + l) * DD + d] = r;
        }
    }
}

// ============================================================================
// K2: structure-bias GEMM, 128-wide n tiles + smem-staged coalesced stores.
//  variant 0 (f=l): g_biasq[bh, f, n]  = q.S[f,n,:] + mask[b,n]
//  variant 1 (f=r): g_biaskT[bh, f, n] = 0.125 * k.S[n,f,:]
// ============================================================================
#define STGW 136   // staging stride in bf16 (272B = 17*16, uint4-aligned rows)

__global__ __launch_bounds__(256) void bias_mma_kernel(
    const float* __restrict__ S, const float* __restrict__ mask, int variant)
{
    __shared__ unsigned As[64][68];
    __shared__ unsigned Ss[128][68];   // also reused as bf16 staging (needs 17408B)

    const int tid  = threadIdx.x;
    const int warp = tid >> 5;
    const int lane = tid & 31;
    const int n0 = blockIdx.x * 128;
    const int f  = blockIdx.y;
    const int mstrip = (warp & 3) * 16;
    const int nh     = (warp >> 2) * 64;
    const int arow   = mstrip + (lane >> 2);

    const float* Aop = (variant == 0) ? g_q : g_k;

    // A tile: 48 real bh rows (zero-pad to 64), already tf32 bits
#pragma unroll
    for (int i = 0; i < 4; i++) {
        const int idx = tid + i * 256;
        const int row = idx >> 4;
        const int c4  = idx & 15;
        if (row < BH) {
            float4 av = *(const float4*)(Aop + ((size_t)row * LL + f) * DD + c4 * 4);
            As[row][c4 * 4 + 0] = __float_as_uint(av.x);
            As[row][c4 * 4 + 1] = __float_as_uint(av.y);
            As[row][c4 * 4 + 2] = __float_as_uint(av.z);
            As[row][c4 * 4 + 3] = __float_as_uint(av.w);
        } else {
            As[row][c4 * 4 + 0] = 0u; As[row][c4 * 4 + 1] = 0u;
            As[row][c4 * 4 + 2] = 0u; As[row][c4 * 4 + 3] = 0u;
        }
    }
    // S tile: 128 n rows
#pragma unroll
    for (int i = 0; i < 8; i++) {
        const int idx = tid + i * 256;
        const int row = idx >> 4;
        const int c4  = idx & 15;
        size_t soff = (variant == 0)
            ? (((size_t)f * LL + n0 + row) * DD + c4 * 4)
            : (((size_t)(n0 + row) * LL + f) * DD + c4 * 4);
        float4 sv = *(const float4*)(S + soff);
        Ss[row][c4 * 4 + 0] = tf32cvt(sv.x); Ss[row][c4 * 4 + 1] = tf32cvt(sv.y);
        Ss[row][c4 * 4 + 2] = tf32cvt(sv.z); Ss[row][c4 * 4 + 3] = tf32cvt(sv.w);
    }
    __syncthreads();

    float acc[8][4];
#pragma unroll
    for (int i = 0; i < 8; i++)
#pragma unroll
        for (int j = 0; j < 4; j++) acc[i][j] = 0.f;

#pragma unroll
    for (int ks = 0; ks < 8; ks++) {
        const int kc = ks * 8 + (lane & 3);
        unsigned a0 = As[arow][kc];
        unsigned a1 = As[arow + 8][kc];
        unsigned a2 = As[arow][kc + 4];
        unsigned a3 = As[arow + 8][kc + 4];
#pragma unroll
        for (int nt = 0; nt < 8; nt++) {
            const int nb = nh + nt * 8 + (lane >> 2);
            unsigned b0 = Ss[nb][kc];
            unsigned b1 = Ss[nb][kc + 4];
            mma_tf32(acc[nt][0], acc[nt][1], acc[nt][2], acc[nt][3],
                     a0, a1, a2, a3, b0, b1);
        }
    }
    __syncthreads();   // all mma reads of Ss done; safe to reuse as staging

    // ---- stage bf16 results: stg[bh][local n], stride STGW ----
    __nv_bfloat16* stg = (__nv_bfloat16*)&Ss[0][0];
#pragma unroll
    for (int nt = 0; nt < 8; nt++) {
        const int col = nh + nt * 8 + 2 * (lane & 3);   // local 0..127
#pragma unroll
        for (int half = 0; half < 2; half++) {
            const int bh = arow + half * 8;
            if (bh >= BH) continue;
            __nv_bfloat162 bv;
            if (variant == 0) {
                const int b_idx = bh / HH;
                bv = __floats2bfloat162_rn(
                    acc[nt][2 * half + 0] + mask[b_idx * LL + n0 + col + 0],
                    acc[nt][2 * half + 1] + mask[b_idx * LL + n0 + col + 1]);
            } else {
                bv = __floats2bfloat162_rn(
                    acc[nt][2 * half + 0] * 0.125f,
                    acc[nt][2 * half + 1] * 0.125f);
            }
            *(__nv_bfloat162*)&stg[bh * STGW + col] = bv;
        }
    }
    __syncthreads();

    // ---- coalesced store: 48 rows x 256B contiguous ----
    __nv_bfloat16* dst_base = (variant == 0) ? g_biasq : g_biaskT;
#pragma unroll
    for (int i = 0; i < 3; i++) {
        const int idx = tid + i * 256;        // 0..767
        const int row = idx >> 4;             // bh 0..47
        const int seg = idx & 15;             // 16 x 8 bf16 = 128 cols
        uint4 v = *(const uint4*)&stg[row * STGW + seg * 8];
        *(uint4*)&dst_base[((size_t)row * LL + f) * LL + n0 + seg * 8] = v;
    }
}

// ============================================================================
// K3: fused flash attention.  75.8 KB smem -> 3 CTAs/SM.
// K/V via cp.async double buffer; biasq + biaskT via register LDG prefetch.
// P@V with P-compensation only (Phi*V + Plo*V).
// ============================================================================
#define RC      32
#define SPW     36
#define QSW     68

// smem layout (float units)
#define OFF_QS    0                       // 64*68 = 4352
#define OFF_KS0   4352                    // 32*68 = 2176
#define OFF_KS1   6528
#define OFF_VH0   8704
#define OFF_VH1   10880
#define OFF_SP    13056                   // 64*36 = 2304
#define OFF_PL    15360                   // 64*36 = 2304
#define OFF_TS    17664                   // 64*34 bf16 = 1088 floats
#define OFF_MS    18752
#define OFF_SU    18816
#define OFF_SC    18880
#define SMEM_FLOATS 18944                 // 75776 B

__global__ __launch_bounds__(256) void fused_attn_kernel(float* __restrict__ out)
{
    extern __shared__ float sm[];
    float* Qs = sm + OFF_QS;
    float* Sp = sm + OFF_SP;
    float* Pl = sm + OFF_PL;
    float* m_state   = sm + OFF_MS;
    float* sum_state = sm + OFF_SU;
    float* scalef    = sm + OFF_SC;

    const int tid  = threadIdx.x;
    const int lane = tid & 31;
    const int warp = tid >> 5;
    const int bh   = blockIdx.y;
    const int l0   = blockIdx.x * 64;

    const int mstrip = (warp & 3) * 16;
    const int nh2    = (warp >> 2) * 16;   // qk N = 32
    const int nhpv   = (warp >> 2) * 32;   // pv N = 64
    const int arow   = mstrip + (lane >> 2);
    const int kcl    = lane & 3;

    // ---- prologue: Q tile (tf32 bits) -> smem ----
#pragma unroll
    for (int i = 0; i < 4; i++) {
        const int idx = tid + i * 256;
        const int row = idx >> 4;
        const int c4  = idx & 15;
        *(float4*)&Qs[row * QSW + c4 * 4] =
            *(const float4*)(g_q + ((size_t)bh * LL + l0 + row) * DD + c4 * 4);
    }
    if (tid < 64) { m_state[tid] = -1e30f; sum_state[tid] = 0.f; }

    const int krow = tid >> 4, kseg = tid & 15;            // K/V staging
    const int trow = tid >> 3, tseg = tid & 7;             // Ts LDG
    const int bql  = tid >> 2, bqc  = (tid & 3) * 8;       // Bq LDG (owner layout)

    auto stage = [&](int rc, int db) {
        float* Ks = sm + (db ? OFF_KS1 : OFF_KS0);
        float* Vh = sm + (db ? OFF_VH1 : OFF_VH0);
#pragma unroll
        for (int i = 0; i < 2; i++) {
            const int row = krow + i * 16;
            const size_t goff = ((size_t)bh * LL + rc + row) * DD + kseg * 4;
            cp16(&Ks[row * QSW + kseg * 4], g_k + goff);
            cp16(&Vh[row * QSW + kseg * 4], g_v + goff);
        }
        asm volatile("cp.async.commit_group;" ::: "memory");
    };
    auto ldg_ts = [&](int rc) -> uint4 {
        return *(const uint4*)(g_biaskT + ((size_t)bh * LL + rc + trow) * LL + l0 + tseg * 8);
    };
    auto ldg_bq = [&](int rc) -> uint4 {
        return *(const uint4*)(g_biasq + ((size_t)bh * LL + l0 + bql) * LL + rc + bqc);
    };

    float accpv[4][4];
#pragma unroll
    for (int i = 0; i < 4; i++)
#pragma unroll
        for (int j = 0; j < 4; j++) accpv[i][j] = 0.f;

    uint4 ts_reg = ldg_ts(0);
    uint4 bq_reg = ldg_bq(0);
    stage(0, 0);

    for (int ci = 0; ci < LL / RC; ci++) {
        const int cur = ci & 1;
        float* Ks = sm + (cur ? OFF_KS1 : OFF_KS0);
        float* Vh = sm + (cur ? OFF_VH1 : OFF_VH0);
        unsigned short* TsL = (unsigned short*)(sm + OFF_TS);

        // wait for chunk cur; barrier also closes reads of buffer cur^1 + TsL
        asm volatile("cp.async.wait_group 0;" ::: "memory");
        __syncthreads();

        uint4 ts_next, bq_next;
        if (ci + 1 < LL / RC) {
            ts_next = ldg_ts((ci + 1) * RC);
            bq_next = ldg_bq((ci + 1) * RC);
            stage((ci + 1) * RC, cur ^ 1);
        }

        // Ts transpose store: TsL[l][r], stride 34 halfwords
        {
            const unsigned short* h = (const unsigned short*)&ts_reg;
#pragma unroll
            for (int j = 0; j < 8; j++)
                TsL[(tseg * 8 + j) * 34 + trow] = h[j];
        }

        // ---- qk mma (pure LDS) ----
        float accqk[2][4];
#pragma unroll
        for (int i = 0; i < 2; i++)
#pragma unroll
            for (int j = 0; j < 4; j++) accqk[i][j] = 0.f;
#pragma unroll
        for (int ks = 0; ks < 8; ks++) {
            const int kc = ks * 8 + kcl;
            unsigned a0 = __float_as_uint(Qs[arow * QSW + kc]);
            unsigned a1 = __float_as_uint(Qs[(arow + 8) * QSW + kc]);
            unsigned a2 = __float_as_uint(Qs[arow * QSW + kc + 4]);
            unsigned a3 = __float_as_uint(Qs[(arow + 8) * QSW + kc + 4]);
#pragma unroll
            for (int nt = 0; nt < 2; nt++) {
                const int nb = nh2 + nt * 8 + (lane >> 2);
                unsigned b0 = __float_as_uint(Ks[nb * QSW + kc]);
                unsigned b1 = __float_as_uint(Ks[nb * QSW + kc + 4]);
                mma_tf32(accqk[nt][0], accqk[nt][1], accqk[nt][2], accqk[nt][3],
                         a0, a1, a2, a3, b0, b1);
            }
        }
#pragma unroll
        for (int nt = 0; nt < 2; nt++) {
            const int col = nh2 + nt * 8 + 2 * (lane & 3);
#pragma unroll
            for (int half = 0; half < 2; half++) {
                const int row = arow + half * 8;
                *(float2*)&Sp[row * SPW + col] =
                    make_float2(accqk[nt][2 * half + 0], accqk[nt][2 * half + 1]);
            }
        }
        __syncthreads();                    // Sp + TsL ready

        // ---- merged stats + P (thread owns l = tid>>2, r = (tid&3)*8..+7) ----
        {
            const int l  = bql;
            const int c0 = bqc;
            const float mv_old = m_state[l];
            float s[8];
            {
                float4 sp0 = *(float4*)&Sp[l * SPW + c0];
                float4 sp1 = *(float4*)&Sp[l * SPW + c0 + 4];
                const __nv_bfloat162* ts2 = (const __nv_bfloat162*)&TsL[l * 34 + c0];
                float2 b0 = bf2(bq_reg.x);
                float2 b1 = bf2(bq_reg.y);
                float2 b2 = bf2(bq_reg.z);
                float2 b3 = bf2(bq_reg.w);
                float2 t0 = __bfloat1622float2(ts2[0]);
                float2 t1 = __bfloat1622float2(ts2[1]);
                float2 t2 = __bfloat1622float2(ts2[2]);
                float2 t3 = __bfloat1622float2(ts2[3]);
                s[0] = sp0.x + b0.x + t0.x;  s[1] = sp0.y + b0.y + t0.y;
                s[2] = sp0.z + b1.x + t1.x;  s[3] = sp0.w + b1.y + t1.y;
                s[4] = sp1.x + b2.x + t2.x;  s[5] = sp1.y + b2.y + t2.y;
                s[6] = sp1.z + b3.x + t3.x;  s[7] = sp1.w + b3.y + t3.y;
            }
            float mc = s[0];
#pragma unroll
            for (int j = 1; j < 8; j++) mc = fmaxf(mc, s[j]);
            mc = fmaxf(mc, __shfl_xor_sync(0xffffffffu, mc, 1));
            mc = fmaxf(mc, __shfl_xor_sync(0xffffffffu, mc, 2));
            const float mnew = fmaxf(mv_old, mc);
            float e = 0.f;
            float pv[8], ph[8];
#pragma unroll
            for (int j = 0; j < 8; j++) {
                pv[j] = __expf(s[j] - mnew);
                e += pv[j];
                ph[j] = __uint_as_float(tf32cvt(pv[j]));
            }
            float4 p0, p1, q0, q1;
            p0.x = ph[0]; p0.y = ph[1]; p0.z = ph[2]; p0.w = ph[3];
            p1.x = ph[4]; p1.y = ph[5]; p1.z = ph[6]; p1.w = ph[7];
            q0.x = __uint_as_float(tf32cvt(pv[0] - ph[0]));
            q0.y = __uint_as_float(tf32cvt(pv[1] - ph[1]));
            q0.z = __uint_as_float(tf32cvt(pv[2] - ph[2]));
            q0.w = __uint_as_float(tf32cvt(pv[3] - ph[3]));
            q1.x = __uint_as_float(tf32cvt(pv[4] - ph[4]));
            q1.y = __uint_as_float(tf32cvt(pv[5] - ph[5]));
            q1.z = __uint_as_float(tf32cvt(pv[6] - ph[6]));
            q1.w = __uint_as_float(tf32cvt(pv[7] - ph[7]));
            *(float4*)&Sp[l * SPW + c0]     = p0;
            *(float4*)&Sp[l * SPW + c0 + 4] = p1;
            *(float4*)&Pl[l * SPW + c0]     = q0;
            *(float4*)&Pl[l * SPW + c0 + 4] = q1;
            e += __shfl_xor_sync(0xffffffffu, e, 1);
            e += __shfl_xor_sync(0xffffffffu, e, 2);
            if ((tid & 3) == 0) {
                const float sc = __expf(mv_old - mnew);
                scalef[l] = sc;
                sum_state[l] = sum_state[l] * sc + e;
                m_state[l] = mnew;
            }
        }
        __syncthreads();                    // P + scalef ready

        // ---- rescale + P-compensated P@V mma ----
        {
            const float sc0 = scalef[arow];
            const float sc1 = scalef[arow + 8];
#pragma unroll
            for (int nt = 0; nt < 4; nt++) {
                accpv[nt][0] *= sc0; accpv[nt][1] *= sc0;
                accpv[nt][2] *= sc1; accpv[nt][3] *= sc1;
            }
        }
#pragma unroll
        for (int ks = 0; ks < 4; ks++) {
            const int kc = ks * 8 + kcl;
            unsigned ah0 = __float_as_uint(Sp[arow * SPW + kc]);
            unsigned ah1 = __float_as_uint(Sp[(arow + 8) * SPW + kc]);
            unsigned ah2 = __float_as_uint(Sp[arow * SPW + kc + 4]);
            unsigned ah3 = __float_as_uint(Sp[(arow + 8) * SPW + kc + 4]);
            unsigned al0 = __float_as_uint(Pl[arow * SPW + kc]);
            unsigned al1 = __float_as_uint(Pl[(arow + 8) * SPW + kc]);
            unsigned al2 = __float_as_uint(Pl[arow * SPW + kc + 4]);
            unsigned al3 = __float_as_uint(Pl[(arow + 8) * SPW + kc + 4]);
#pragma unroll
            for (int nt = 0; nt < 4; nt++) {
                const int nb = nhpv + nt * 8 + (lane >> 2);
                unsigned bh0 = __float_as_uint(Vh[(ks * 8 + kcl) * QSW + nb]);
                unsigned bh1 = __float_as_uint(Vh[(ks * 8 + kcl + 4) * QSW + nb]);
                mma_tf32(accpv[nt][0], accpv[nt][1], accpv[nt][2], accpv[nt][3],
                         ah0, ah1, ah2, ah3, bh0, bh1);
                mma_tf32(accpv[nt][0], accpv[nt][1], accpv[nt][2], accpv[nt][3],
                         al0, al1, al2, al3, bh0, bh1);
            }
        }
        ts_reg = ts_next;
        bq_reg = bq_next;
    }

    // ---- write out[b, l, h*64 + d] ----
    const int b_idx = bh / HH;
    const int h     = bh % HH;
#pragma unroll
    for (int half = 0; half < 2; half++) {
        const int row = arow + half * 8;
        const float inv = 1.f / sum_state[row];
        const int l = l0 + row;
#pragma unroll
        for (int nt = 0; nt < 4; nt++) {
            const int col = nhpv + nt * 8 + 2 * (lane & 3);
            float2 r;
            r.x = accpv[nt][2 * half + 0] * inv;
            r.y = accpv[nt][2 * half + 1] * inv;
            *(float2*)&out[((size_t)(b_idx * LL + l)) * HIDD + h * DD + col] = r;
        }
    }
}

// ============================================================================
// launch — fork/join streams: (q->bias0) || (k->bias1) || v, then fused.
// ============================================================================
extern "C" void kernel_launch(void* const* d_in, const int* in_sizes, int n_in,
                              void* d_out, int out_size)
{
    (void)in_sizes; (void)n_in; (void)out_size;
    const float* hidden = (const float*)d_in[0];
    const float* mask   = (const float*)d_in[1];
    const float* S      = (const float*)d_in[2];
    const float* Wq     = (const float*)d_in[3];
    const float* bq     = (const float*)d_in[4];
    const float* Wk     = (const float*)d_in[5];
    const float* bk     = (const float*)d_in[6];
    const float* Wv     = (const float*)d_in[7];
    const float* bv     = (const float*)d_in[8];
    float* out = (float*)d_out;

    static cudaStream_t s1 = 0, s2 = 0;
    static cudaEvent_t eR = 0, e1 = 0, e2 = 0;
    static int init_done = 0;
    if (!init_done) {
        cudaFuncSetAttribute(fused_attn_kernel,
                             cudaFuncAttributeMaxDynamicSharedMemorySize,
                             SMEM_FLOATS * (int)sizeof(float));
        cudaStreamCreateWithFlags(&s1, cudaStreamNonBlocking);
        cudaStreamCreateWithFlags(&s2, cudaStreamNonBlocking);
        cudaEventCreateWithFlags(&eR, cudaEventDisableTiming);
        cudaEventCreateWithFlags(&e1, cudaEventDisableTiming);
        cudaEventCreateWithFlags(&e2, cudaEventDisableTiming);
        init_done = 1;
    }

    dim3 g1(64, 12);
    dim3 g2(8, 1024);

    cudaEventRecord(eR, 0);
    cudaStreamWaitEvent(s1, eR, 0);
    cudaStreamWaitEvent(s2, eR, 0);

    // chain A (stream 0): q proj -> q-side bias
    qkv_mma_kernel<<<g1, 256, 0, 0>>>(hidden, Wq, bq, 0);
    bias_mma_kernel<<<g2, 256, 0, 0>>>(S, mask, 0);

    // chain B (s1): k proj -> k-side bias
    qkv_mma_kernel<<<g1, 256, 0, s1>>>(hidden, Wk, bk, 1);
    bias_mma_kernel<<<g2, 256, 0, s1>>>(S, mask, 1);

    // chain C (s2): v proj
    qkv_mma_kernel<<<g1, 256, 0, s2>>>(hidden, Wv, bv, 2);

    cudaEventRecord(e1, s1);
    cudaEventRecord(e2, s2);
    cudaStreamWaitEvent(0, e1, 0);
    cudaStreamWaitEvent(0, e2, 0);

    dim3 g3(16, 48);
    fused_attn_kernel<<<g3, 256, SMEM_FLOATS * sizeof(float)>>>(out);
}

// round 12
// speedup vs baseline: 1.4126x; 1.0069x over previous
#include <cuda_runtime.h>
#include <cuda_bf16.h>
#include <math.h>

#define BB   4
#define LL   1024
#define HIDD 768
#define HH   12
#define DD   64
#define BH   (BB*HH)

// ---- scratch (device globals; no allocation allowed) ----
__device__ float g_q[BH * LL * DD];                        // [bh, l, d] tf32 bits (pre-scaled 0.125)
__device__ float g_k[BH * LL * DD];                        // [bh, l, d] tf32 bits
__device__ float g_v[BH * LL * DD];                        // [bh, l, d] tf32 bits
__device__ __nv_bfloat16 g_biasq[(size_t)BH * LL * LL];    // [bh, l, r] = qS/8 + mask
__device__ __nv_bfloat16 g_biaskT[(size_t)BH * LL * LL];   // [bh, r, l] = kS/8

// ---------------- helpers ----------------
__device__ __forceinline__ unsigned tf32cvt(float x) {
    unsigned u;
    asm("cvt.rna.tf32.f32 %0, %1;" : "=r"(u) : "f"(x));
    return u;
}
__device__ __forceinline__ void mma_tf32(float& c0, float& c1, float& c2, float& c3,
                                         unsigned a0, unsigned a1, unsigned a2, unsigned a3,
                                         unsigned b0, unsigned b1) {
    asm("mma.sync.aligned.m16n8k8.row.col.f32.tf32.tf32.f32 "
        "{%0,%1,%2,%3},{%4,%5,%6,%7},{%8,%9},{%0,%1,%2,%3};"
        : "+f"(c0), "+f"(c1), "+f"(c2), "+f"(c3)
        : "r"(a0), "r"(a1), "r"(a2), "r"(a3), "r"(b0), "r"(b1));
}
__device__ __forceinline__ void cp16(const void* smem_dst, const void* gsrc) {
    unsigned sa = (unsigned)__cvta_generic_to_shared(smem_dst);
    asm volatile("cp.async.cg.shared.global [%0], [%1], 16;" :: "r"(sa), "l"(gsrc));
}
__device__ __forceinline__ float2 bf2(unsigned u) {
    __nv_bfloat162 h = *reinterpret_cast<__nv_bfloat162*>(&u);
    return __bfloat1622float2(h);
}

// ============================================================================
// K1: QKV projection, tf32 mma, register double-buffered staging.
// Outputs stored as tf32-bit floats (consumers do zero conversions).
// ============================================================================
__global__ __launch_bounds__(256) void qkv_mma_kernel(
    const float* __restrict__ X,
    const float* __restrict__ W,
    const float* __restrict__ bias,
    int which)
{
    __shared__ unsigned Xs[64][68];
    __shared__ unsigned Ws[64][68];

    const int tid  = threadIdx.x;
    const int warp = tid >> 5;
    const int lane = tid & 31;
    const int m0 = blockIdx.x * 64;
    const int n0 = blockIdx.y * 64;
    const int mstrip = (warp & 3) * 16;
    const int nh     = (warp >> 2) * 32;

    float acc[4][4];
#pragma unroll
    for (int i = 0; i < 4; i++)
#pragma unroll
        for (int j = 0; j < 4; j++) acc[i][j] = 0.f;

    float4 xr[4], wr[4];
#pragma unroll
    for (int i = 0; i < 4; i++) {
        const int idx = tid + i * 256;
        const int row = idx >> 4;
        const int c4  = idx & 15;
        xr[i] = *(const float4*)(X + (size_t)(m0 + row) * HIDD + c4 * 4);
        wr[i] = *(const float4*)(W + (size_t)(n0 + row) * HIDD + c4 * 4);
    }

    for (int k0 = 0; k0 < HIDD; k0 += 64) {
        __syncthreads();
#pragma unroll
        for (int i = 0; i < 4; i++) {
            const int idx = tid + i * 256;
            const int row = idx >> 4;
            const int c4  = idx & 15;
            Xs[row][c4 * 4 + 0] = tf32cvt(xr[i].x); Xs[row][c4 * 4 + 1] = tf32cvt(xr[i].y);
            Xs[row][c4 * 4 + 2] = tf32cvt(xr[i].z); Xs[row][c4 * 4 + 3] = tf32cvt(xr[i].w);
            Ws[row][c4 * 4 + 0] = tf32cvt(wr[i].x); Ws[row][c4 * 4 + 1] = tf32cvt(wr[i].y);
            Ws[row][c4 * 4 + 2] = tf32cvt(wr[i].z); Ws[row][c4 * 4 + 3] = tf32cvt(wr[i].w);
        }
        __syncthreads();
        if (k0 + 64 < HIDD) {
#pragma unroll
            for (int i = 0; i < 4; i++) {
                const int idx = tid + i * 256;
                const int row = idx >> 4;
                const int c4  = idx & 15;
                xr[i] = *(const float4*)(X + (size_t)(m0 + row) * HIDD + k0 + 64 + c4 * 4);
                wr[i] = *(const float4*)(W + (size_t)(n0 + row) * HIDD + k0 + 64 + c4 * 4);
            }
        }
#pragma unroll
        for (int ks = 0; ks < 8; ks++) {
            const int kc = ks * 8 + (lane & 3);
            unsigned a0 = Xs[mstrip + (lane >> 2)][kc];
            unsigned a1 = Xs[mstrip + (lane >> 2) + 8][kc];
            unsigned a2 = Xs[mstrip + (lane >> 2)][kc + 4];
            unsigned a3 = Xs[mstrip + (lane >> 2) + 8][kc + 4];
#pragma unroll
            for (int nt = 0; nt < 4; nt++) {
                const int nb = nh + nt * 8;
                unsigned b0 = Ws[nb + (lane >> 2)][kc];
                unsigned b1 = Ws[nb + (lane >> 2)][kc + 4];
                mma_tf32(acc[nt][0], acc[nt][1], acc[nt][2], acc[nt][3],
                         a0, a1, a2, a3, b0, b1);
            }
        }
    }

    float* out = (which == 0) ? g_q : (which == 1) ? g_k : g_v;
    const float scale = (which == 0) ? 0.125f : 1.0f;
    const int row0 = m0 + mstrip + (lane >> 2);
#pragma unroll
    for (int nt = 0; nt < 4; nt++) {
        const int col = n0 + nh + nt * 8 + 2 * (lane & 3);
        const int h = col >> 6;
        const int d = col & 63;
#pragma unroll
        for (int half = 0; half < 2; half++) {
            const int row = row0 + half * 8;
            const int b_idx = row >> 10;
            const int l     = row & (LL - 1);
            float2 r;
            r.x = __uint_as_float(tf32cvt((acc[nt][2 * half + 0] + bias[col + 0]) * scale));
            r.y = __uint_as_float(tf32cvt((acc[nt][2 * half + 1] + bias[col + 1]) * scale));
            *(float2*)&out[(((size_t)b_idx * HH + h) * LL + l) * DD + d] = r;
        }
    }
}

// ============================================================================
// K2: combined structure-bias GEMM with L2 supertiling.
// grid = (2048, 8): y = l-supertile (128 l's = 32MB of S, L2-resident).
//   x < 1024  -> variant 0: f = y*128 + (x>>3),  n0 = (x&7)*128   (reads S[f, n, :])
//   x >= 1024 -> variant 1: f = x - 1024,        n0 = y*128       (reads S[n, f, :])
// Launch order (x-major) makes variant0 warm L2 for variant1 within a supertile.
// ============================================================================
#define STGW 136   // staging stride in bf16

__global__ __launch_bounds__(256) void bias_mma_kernel(
    const float* __restrict__ S, const float* __restrict__ mask)
{
    __shared__ unsigned As[64][68];
    __shared__ unsigned Ss[128][68];   // reused as bf16 staging

    const int tid  = threadIdx.x;
    const int warp = tid >> 5;
    const int lane = tid & 31;

    const int x    = blockIdx.x;
    const int ysup = blockIdx.y;
    int variant, f, n0;
    if (x < 1024) { variant = 0; f = ysup * 128 + (x >> 3); n0 = (x & 7) * 128; }
    else          { variant = 1; f = x - 1024;              n0 = ysup * 128;    }

    const int nh   = (warp >> 2) * 64;
    const int arow = (warp & 3) * 16 + (lane >> 2);

    const float* Aop = (variant == 0) ? g_q : g_k;

    // A tile: 48 real bh rows (zero-pad to 64), already tf32 bits
#pragma unroll
    for (int i = 0; i < 4; i++) {
        const int idx = tid + i * 256;
        const int row = idx >> 4;
        const int c4  = idx & 15;
        if (row < BH) {
            float4 av = *(const float4*)(Aop + ((size_t)row * LL + f) * DD + c4 * 4);
            As[row][c4 * 4 + 0] = __float_as_uint(av.x);
            As[row][c4 * 4 + 1] = __float_as_uint(av.y);
            As[row][c4 * 4 + 2] = __float_as_uint(av.z);
            As[row][c4 * 4 + 3] = __float_as_uint(av.w);
        } else {
            As[row][c4 * 4 + 0] = 0u; As[row][c4 * 4 + 1] = 0u;
            As[row][c4 * 4 + 2] = 0u; As[row][c4 * 4 + 3] = 0u;
        }
    }
    // S tile: 128 n rows
#pragma unroll
    for (int i = 0; i < 8; i++) {
        const int idx = tid + i * 256;
        const int row = idx >> 4;
        const int c4  = idx & 15;
        size_t soff = (variant == 0)
            ? (((size_t)f * LL + n0 + row) * DD + c4 * 4)
            : (((size_t)(n0 + row) * LL + f) * DD + c4 * 4);
        float4 sv = *(const float4*)(S + soff);
        Ss[row][c4 * 4 + 0] = tf32cvt(sv.x); Ss[row][c4 * 4 + 1] = tf32cvt(sv.y);
        Ss[row][c4 * 4 + 2] = tf32cvt(sv.z); Ss[row][c4 * 4 + 3] = tf32cvt(sv.w);
    }
    __syncthreads();

    float acc[8][4];
#pragma unroll
    for (int i = 0; i < 8; i++)
#pragma unroll
        for (int j = 0; j < 4; j++) acc[i][j] = 0.f;

#pragma unroll
    for (int ks = 0; ks < 8; ks++) {
        const int kc = ks * 8 + (lane & 3);
        unsigned a0 = As[arow][kc];
        unsigned a1 = As[arow + 8][kc];
        unsigned a2 = As[arow][kc + 4];
        unsigned a3 = As[arow + 8][kc + 4];
#pragma unroll
        for (int nt = 0; nt < 8; nt++) {
            const int nb = nh + nt * 8 + (lane >> 2);
            unsigned b0 = Ss[nb][kc];
            unsigned b1 = Ss[nb][kc + 4];
            mma_tf32(acc[nt][0], acc[nt][1], acc[nt][2], acc[nt][3],
                     a0, a1, a2, a3, b0, b1);
        }
    }
    __syncthreads();   // all mma reads of Ss done; reuse as staging

    // ---- stage bf16 results ----
    __nv_bfloat16* stg = (__nv_bfloat16*)&Ss[0][0];
#pragma unroll
    for (int nt = 0; nt < 8; nt++) {
        const int col = nh + nt * 8 + 2 * (lane & 3);
#pragma unroll
        for (int half = 0; half < 2; half++) {
            const int bh = arow + half * 8;
            if (bh >= BH) continue;
            __nv_bfloat162 bv;
            if (variant == 0) {
                const int b_idx = bh / HH;
                bv = __floats2bfloat162_rn(
                    acc[nt][2 * half + 0] + mask[b_idx * LL + n0 + col + 0],
                    acc[nt][2 * half + 1] + mask[b_idx * LL + n0 + col + 1]);
            } else {
                bv = __floats2bfloat162_rn(
                    acc[nt][2 * half + 0] * 0.125f,
                    acc[nt][2 * half + 1] * 0.125f);
            }
            *(__nv_bfloat162*)&stg[bh * STGW + col] = bv;
        }
    }
    __syncthreads();

    // ---- coalesced store: 48 rows x 256B contiguous ----
    __nv_bfloat16* dst_base = (variant == 0) ? g_biasq : g_biaskT;
#pragma unroll
    for (int i = 0; i < 3; i++) {
        const int idx = tid + i * 256;
        const int row = idx >> 4;             // bh 0..47
        const int seg = idx & 15;
        uint4 v = *(const uint4*)&stg[row * STGW + seg * 8];
        *(uint4*)&dst_base[((size_t)row * LL + f) * LL + n0 + seg * 8] = v;
    }
}

// ============================================================================
// K3: fused flash attention.  75.8 KB smem, forced 3 CTAs/SM.
// K/V via cp.async double buffer; biasq + biaskT via register LDG prefetch.
// P@V with P-compensation (Phi*V + Plo*V).
// ============================================================================
#define RC      32
#define SPW     36
#define QSW     68

// smem layout (float units)
#define OFF_QS    0
#define OFF_KS0   4352
#define OFF_KS1   6528
#define OFF_VH0   8704
#define OFF_VH1   10880
#define OFF_SP    13056
#define OFF_PL    15360
#define OFF_TS    17664
#define OFF_MS    18752
#define OFF_SU    18816
#define OFF_SC    18880
#define SMEM_FLOATS 18944                 // 75776 B

__global__ __launch_bounds__(256, 3) void fused_attn_kernel(float* __restrict__ out)
{
    extern __shared__ float sm[];
    float* Qs = sm + OFF_QS;
    float* Sp = sm + OFF_SP;
    float* Pl = sm + OFF_PL;
    float* m_state   = sm + OFF_MS;
    float* sum_state = sm + OFF_SU;
    float* scalef    = sm + OFF_SC;

    const int tid  = threadIdx.x;
    const int lane = tid & 31;
    const int warp = tid >> 5;
    const int bh   = blockIdx.y;
    const int l0   = blockIdx.x * 64;

    const int mstrip = (warp & 3) * 16;
    const int nh2    = (warp >> 2) * 16;
    const int nhpv   = (warp >> 2) * 32;
    const int arow   = mstrip + (lane >> 2);
    const int kcl    = lane & 3;

    // ---- prologue: Q tile (tf32 bits) -> smem ----
#pragma unroll
    for (int i = 0; i < 4; i++) {
        const int idx = tid + i * 256;
        const int row = idx >> 4;
        const int c4  = idx & 15;
        *(float4*)&Qs[row * QSW + c4 * 4] =
            *(const float4*)(g_q + ((size_t)bh * LL + l0 + row) * DD + c4 * 4);
    }
    if (tid < 64) { m_state[tid] = -1e30f; sum_state[tid] = 0.f; }

    const int krow = tid >> 4, kseg = tid & 15;
    const int trow = tid >> 3, tseg = tid & 7;
    const int bql  = tid >> 2, bqc  = (tid & 3) * 8;

    auto stage = [&](int rc, int db) {
        float* Ks = sm + (db ? OFF_KS1 : OFF_KS0);
        float* Vh = sm + (db ? OFF_VH1 : OFF_VH0);
#pragma unroll
        for (int i = 0; i < 2; i++) {
            const int row = krow + i * 16;
            const size_t goff = ((size_t)bh * LL + rc + row) * DD + kseg * 4;
            cp16(&Ks[row * QSW + kseg * 4], g_k + goff);
            cp16(&Vh[row * QSW + kseg * 4], g_v + goff);
        }
        asm volatile("cp.async.commit_group;" ::: "memory");
    };
    auto ldg_ts = [&](int rc) -> uint4 {
        return *(const uint4*)(g_biaskT + ((size_t)bh * LL + rc + trow) * LL + l0 + tseg * 8);
    };
    auto ldg_bq = [&](int rc) -> uint4 {
        return *(const uint4*)(g_biasq + ((size_t)bh * LL + l0 + bql) * LL + rc + bqc);
    };

    float accpv[4][4];
#pragma unroll
    for (int i = 0; i < 4; i++)
#pragma unroll
        for (int j = 0; j < 4; j++) accpv[i][j] = 0.f;

    uint4 ts_reg = ldg_ts(0);
    uint4 bq_reg = ldg_bq(0);
    stage(0, 0);

    for (int ci = 0; ci < LL / RC; ci++) {
        const int cur = ci & 1;
        float* Ks = sm + (cur ? OFF_KS1 : OFF_KS0);
        float* Vh = sm + (cur ? OFF_VH1 : OFF_VH0);
        unsigned short* TsL = (unsigned short*)(sm + OFF_TS);

        // TsL writes are safe before the barrier: all stats reads of the prior
        // chunk completed before its pre-PV sync, which every thread has passed.
        {
            const unsigned short* h = (const unsigned short*)&ts_reg;
#pragma unroll
            for (int j = 0; j < 8; j++)
                TsL[(tseg * 8 + j) * 34 + trow] = h[j];
        }

        asm volatile("cp.async.wait_group 0;" ::: "memory");
        __syncthreads();

        uint4 ts_next, bq_next;
        if (ci + 1 < LL / RC) {
            ts_next = ldg_ts((ci + 1) * RC);
            bq_next = ldg_bq((ci + 1) * RC);
            stage((ci + 1) * RC, cur ^ 1);
        }

        // ---- qk mma (pure LDS) ----
        float accqk[2][4];
#pragma unroll
        for (int i = 0; i < 2; i++)
#pragma unroll
            for (int j = 0; j < 4; j++) accqk[i][j] = 0.f;
#pragma unroll
        for (int ks = 0; ks < 8; ks++) {
            const int kc = ks * 8 + kcl;
            unsigned a0 = __float_as_uint(Qs[arow * QSW + kc]);
            unsigned a1 = __float_as_uint(Qs[(arow + 8) * QSW + kc]);
            unsigned a2 = __float_as_uint(Qs[arow * QSW + kc + 4]);
            unsigned a3 = __float_as_uint(Qs[(arow + 8) * QSW + kc + 4]);
#pragma unroll
            for (int nt = 0; nt < 2; nt++) {
                const int nb = nh2 + nt * 8 + (lane >> 2);
                unsigned b0 = __float_as_uint(Ks[nb * QSW + kc]);
                unsigned b1 = __float_as_uint(Ks[nb * QSW + kc + 4]);
                mma_tf32(accqk[nt][0], accqk[nt][1], accqk[nt][2], accqk[nt][3],
                         a0, a1, a2, a3, b0, b1);
            }
        }
#pragma unroll
        for (int nt = 0; nt < 2; nt++) {
            const int col = nh2 + nt * 8 + 2 * (lane & 3);
#pragma unroll
            for (int half = 0; half < 2; half++) {
                const int row = arow + half * 8;
                *(float2*)&Sp[row * SPW + col] =
                    make_float2(accqk[nt][2 * half + 0], accqk[nt][2 * half + 1]);
            }
        }
        __syncthreads();                    // Sp + TsL ready

        // ---- merged stats + P ----
        {
            const int l  = bql;
            const int c0 = bqc;
            const float mv_old = m_state[l];
            float s[8];
            {
                float4 sp0 = *(float4*)&Sp[l * SPW + c0];
                float4 sp1 = *(float4*)&Sp[l * SPW + c0 + 4];
                const __nv_bfloat162* ts2 = (const __nv_bfloat162*)&TsL[l * 34 + c0];
                float2 b0 = bf2(bq_reg.x);
                float2 b1 = bf2(bq_reg.y);
                float2 b2 = bf2(bq_reg.z);
                float2 b3 = bf2(bq_reg.w);
                float2 t0 = __bfloat1622float2(ts2[0]);
                float2 t1 = __bfloat1622float2(ts2[1]);
                float2 t2 = __bfloat1622float2(ts2[2]);
                float2 t3 = __bfloat1622float2(ts2[3]);
                s[0] = sp0.x + b0.x + t0.x;  s[1] = sp0.y + b0.y + t0.y;
                s[2] = sp0.z + b1.x + t1.x;  s[3] = sp0.w + b1.y + t1.y;
                s[4] = sp1.x + b2.x + t2.x;  s[5] = sp1.y + b2.y + t2.y;
                s[6] = sp1.z + b3.x + t3.x;  s[7] = sp1.w + b3.y + t3.y;
            }
            float mc = s[0];
#pragma unroll
            for (int j = 1; j < 8; j++) mc = fmaxf(mc, s[j]);
            mc = fmaxf(mc, __shfl_xor_sync(0xffffffffu, mc, 1));
            mc = fmaxf(mc, __shfl_xor_sync(0xffffffffu, mc, 2));
            const float mnew = fmaxf(mv_old, mc);
            float e = 0.f;
            float pv[8], ph[8];
#pragma unroll
            for (int j = 0; j < 8; j++) {
                pv[j] = __expf(s[j] - mnew);
                e += pv[j];
                ph[j] = __uint_as_float(tf32cvt(pv[j]));
            }
            float4 p0, p1, q0, q1;
            p0.x = ph[0]; p0.y = ph[1]; p0.z = ph[2]; p0.w = ph[3];
            p1.x = ph[4]; p1.y = ph[5]; p1.z = ph[6]; p1.w = ph[7];
            q0.x = __uint_as_float(tf32cvt(pv[0] - ph[0]));
            q0.y = __uint_as_float(tf32cvt(pv[1] - ph[1]));
            q0.z = __uint_as_float(tf32cvt(pv[2] - ph[2]));
            q0.w = __uint_as_float(tf32cvt(pv[3] - ph[3]));
            q1.x = __uint_as_float(tf32cvt(pv[4] - ph[4]));
            q1.y = __uint_as_float(tf32cvt(pv[5] - ph[5]));
            q1.z = __uint_as_float(tf32cvt(pv[6] - ph[6]));
            q1.w = __uint_as_float(tf32cvt(pv[7] - ph[7]));
            *(float4*)&Sp[l * SPW + c0]     = p0;
            *(float4*)&Sp[l * SPW + c0 + 4] = p1;
            *(float4*)&Pl[l * SPW + c0]     = q0;
            *(float4*)&Pl[l * SPW + c0 + 4] = q1;
            e += __shfl_xor_sync(0xffffffffu, e, 1);
            e += __shfl_xor_sync(0xffffffffu, e, 2);
            if ((tid & 3) == 0) {
                const float sc = __expf(mv_old - mnew);
                scalef[l] = sc;
                sum_state[l] = sum_state[l] * sc + e;
                m_state[l] = mnew;
            }
        }
        __syncthreads();                    // P + scalef ready

        // ---- rescale + P-compensated P@V mma ----
        {
            const float sc0 = scalef[arow];
            const float sc1 = scalef[arow + 8];
#pragma unroll
            for (int nt = 0; nt < 4; nt++) {
                accpv[nt][0] *= sc0; accpv[nt][1] *= sc0;
                accpv[nt][2] *= sc1; accpv[nt][3] *= sc1;
            }
        }
#pragma unroll
        for (int ks = 0; ks < 4; ks++) {
            const int kc = ks * 8 + kcl;
            unsigned ah0 = __float_as_uint(Sp[arow * SPW + kc]);
            unsigned ah1 = __float_as_uint(Sp[(arow + 8) * SPW + kc]);
            unsigned ah2 = __float_as_uint(Sp[arow * SPW + kc + 4]);
            unsigned ah3 = __float_as_uint(Sp[(arow + 8) * SPW + kc + 4]);
            unsigned al0 = __float_as_uint(Pl[arow * SPW + kc]);
            unsigned al1 = __float_as_uint(Pl[(arow + 8) * SPW + kc]);
            unsigned al2 = __float_as_uint(Pl[arow * SPW + kc + 4]);
            unsigned al3 = __float_as_uint(Pl[(arow + 8) * SPW + kc + 4]);
#pragma unroll
            for (int nt = 0; nt < 4; nt++) {
                const int nb = nhpv + nt * 8 + (lane >> 2);
                unsigned bh0 = __float_as_uint(Vh[(ks * 8 + kcl) * QSW + nb]);
                unsigned bh1 = __float_as_uint(Vh[(ks * 8 + kcl + 4) * QSW + nb]);
                mma_tf32(accpv[nt][0], accpv[nt][1], accpv[nt][2], accpv[nt][3],
                         ah0, ah1, ah2, ah3, bh0, bh1);
                mma_tf32(accpv[nt][0], accpv[nt][1], accpv[nt][2], accpv[nt][3],
                         al0, al1, al2, al3, bh0, bh1);
            }
        }
        ts_reg = ts_next;
        bq_reg = bq_next;
    }

    // ---- write out[b, l, h*64 + d] ----
    const int b_idx = bh / HH;
    const int h     = bh % HH;
#pragma unroll
    for (int half = 0; half < 2; half++) {
        const int row = arow + half * 8;
        const float inv = 1.f / sum_state[row];
        const int l = l0 + row;
#pragma unroll
        for (int nt = 0; nt < 4; nt++) {
            const int col = nhpv + nt * 8 + 2 * (lane & 3);
            float2 r;
            r.x = accpv[nt][2 * half + 0] * inv;
            r.y = accpv[nt][2 * half + 1] * inv;
            *(float2*)&out[((size_t)(b_idx * LL + l)) * HIDD + h * DD + col] = r;
        }
    }
}

// ============================================================================
// launch — q || k || v projections; combined bias after (q,k); fused after all.
// ============================================================================
extern "C" void kernel_launch(void* const* d_in, const int* in_sizes, int n_in,
                              void* d_out, int out_size)
{
    (void)in_sizes; (void)n_in; (void)out_size;
    const float* hidden = (const float*)d_in[0];
    const float* mask   = (const float*)d_in[1];
    const float* S      = (const float*)d_in[2];
    const float* Wq     = (const float*)d_in[3];
    const float* bq     = (const float*)d_in[4];
    const float* Wk     = (const float*)d_in[5];
    const float* bk     = (const float*)d_in[6];
    const float* Wv     = (const float*)d_in[7];
    const float* bv     = (const float*)d_in[8];
    float* out = (float*)d_out;

    static cudaStream_t s1 = 0, s2 = 0;
    static cudaEvent_t eR = 0, e1 = 0, e2 = 0;
    static int init_done = 0;
    if (!init_done) {
        cudaFuncSetAttribute(fused_attn_kernel,
                             cudaFuncAttributeMaxDynamicSharedMemorySize,
                             SMEM_FLOATS * (int)sizeof(float));
        cudaStreamCreateWithFlags(&s1, cudaStreamNonBlocking);
        cudaStreamCreateWithFlags(&s2, cudaStreamNonBlocking);
        cudaEventCreateWithFlags(&eR, cudaEventDisableTiming);
        cudaEventCreateWithFlags(&e1, cudaEventDisableTiming);
        cudaEventCreateWithFlags(&e2, cudaEventDisableTiming);
        init_done = 1;
    }

    dim3 g1(64, 12);

    cudaEventRecord(eR, 0);
    cudaStreamWaitEvent(s1, eR, 0);
    cudaStreamWaitEvent(s2, eR, 0);

    // projections: q on stream 0, k on s1, v on s2
    qkv_mma_kernel<<<g1, 256, 0, 0>>>(hidden, Wq, bq, 0);
    qkv_mma_kernel<<<g1, 256, 0, s1>>>(hidden, Wk, bk, 1);
    qkv_mma_kernel<<<g1, 256, 0, s2>>>(hidden, Wv, bv, 2);

    // bias needs q AND k
    cudaEventRecord(e1, s1);
    cudaStreamWaitEvent(0, e1, 0);
    dim3 g2(2048, 8);
    bias_mma_kernel<<<g2, 256, 0, 0>>>(S, mask);

    // fused needs everything
    cudaEventRecord(e2, s2);
    cudaStreamWaitEvent(0, e2, 0);
    dim3 g3(16, 48);
    fused_attn_kernel<<<g3, 256, SMEM_FLOATS * sizeof(float)>>>(out);
}